// round 11
// baseline (speedup 1.0000x reference)
#include <cuda_runtime.h>
#include <cuda_fp16.h>
#include <cstdint>

#define E_EDGES 131072
#define INS 128
#define OUTS 128
#define NH 8
#define NG 32          /* tau(4) x etype(8) combined groups */
#define ML 240
#define TILE 128
#define MAXBLK (E_EDGES / TILE + NG)   /* 1056 */

#define RTE_BLKS   120
#define HIST_BLKS  512
#define WC_BLKS    512
#define SETUP_GRID (RTE_BLKS + HIST_BLKS + WC_BLKS)   /* 1144 */

// ---------------- device scratch ----------------
__device__ int   g_perm[MAXBLK * TILE];
__device__ int   g_counts[NG];         // zero at load; self-zeroed each replay
__device__ int   g_cursor[NG];
__device__ int   g_done;               // zero at load; self-zeroed each replay
__device__ int   g_blk_info[MAXBLK];   // g | (valid<<8), or -1
__device__ float g_rte[ML * INS];
__device__ __half g_Batt[NG * 16384];  // combined [g][n][k] fp16 (mu/4 folded)
__device__ __half g_Bmsg[NG * 16384];
__device__ float g_bias_att[NG * OUTS];
__device__ float g_bias_msg[NG * OUTS];

// ---------------- helpers ----------------
__device__ __forceinline__ uint32_t smem_u32(const void* p) {
    uint32_t a;
    asm("{ .reg .u64 t; cvta.to.shared.u64 t, %1; cvt.u32.u64 %0, t; }"
        : "=r"(a) : "l"(p));
    return a;
}
__device__ __forceinline__ void ldmx4(uint32_t* r, uint32_t addr) {
    asm volatile("ldmatrix.sync.aligned.m8n8.x4.shared.b16 {%0,%1,%2,%3}, [%4];"
                 : "=r"(r[0]), "=r"(r[1]), "=r"(r[2]), "=r"(r[3]) : "r"(addr));
}
__device__ __forceinline__ void mma16816(float* c, const uint32_t* a, const uint32_t* b) {
    asm volatile(
        "mma.sync.aligned.m16n8k16.row.col.f32.f16.f16.f32 "
        "{%0,%1,%2,%3}, {%4,%5,%6,%7}, {%8,%9}, {%0,%1,%2,%3};"
        : "+f"(c[0]), "+f"(c[1]), "+f"(c[2]), "+f"(c[3])
        : "r"(a[0]), "r"(a[1]), "r"(a[2]), "r"(a[3]), "r"(b[0]), "r"(b[1]));
}
__device__ __forceinline__ void cp_async16(uint32_t saddr, const void* gaddr) {
    asm volatile("cp.async.cg.shared.global [%0], [%1], 16;"
                 :: "r"(saddr), "l"(gaddr));
}
__device__ __forceinline__ void cp_async_commit() {
    asm volatile("cp.async.commit_group;");
}
__device__ __forceinline__ void cp_async_wait0() {
    asm volatile("cp.async.wait_group 0;");
}
__device__ __forceinline__ void stg_cs_128(float* p, float4 v) {
    asm volatile("st.global.cs.v4.f32 [%0], {%1,%2,%3,%4};"
                 :: "l"(p), "f"(v.x), "f"(v.y), "f"(v.z), "f"(v.w) : "memory");
}

// ---------------- fused setup: RTE | histogram(+offsets) | weight-combine ----------------
__global__ void k_setup(const float* __restrict__ emb,
                        const float* __restrict__ linW,
                        const float* __restrict__ linb,
                        const int* __restrict__ etype,
                        const int* __restrict__ tau,
                        const float* __restrict__ K_W, const float* __restrict__ K_b,
                        const float* __restrict__ V_W, const float* __restrict__ V_b,
                        const float* __restrict__ Watt, const float* __restrict__ Wmsg,
                        const float* __restrict__ mu) {
    __shared__ float sW1[16 * 128];   // 8 KB, max of all role needs
    __shared__ float sW2[256];
    __shared__ float sB1[16];
    __shared__ int   sc[NG];
    __shared__ int   isLast;

    int b = blockIdx.x;
    int tid = threadIdx.x;

    if (b < RTE_BLKS) {
        // ---- RTE: rte[d][o] = lin_b[o] + sum_i emb[d][i]*lin_W[o][i]; 2 rows/block
        float* se = sW1;                   // reuse: 2 x 128 floats
        int half = tid >> 7, o = tid & 127;
        int d = b * 2 + half;
        se[half * 128 + o] = emb[d * INS + o];
        __syncthreads();
        float acc = linb[o];
        const float* w = linW + o * INS;
        const float* s = se + half * 128;
#pragma unroll 8
        for (int i = 0; i < INS; i++) acc += s[i] * w[i];
        g_rte[d * INS + o] = acc;
    } else if (b < RTE_BLKS + HIST_BLKS) {
        // ---- histogram; last-done hist block computes offsets
        if (tid < NG) sc[tid] = 0;
        __syncthreads();
        int i = (b - RTE_BLKS) * 256 + tid;
        atomicAdd(&sc[tau[i] * 8 + etype[i]], 1);
        __syncthreads();
        if (tid < NG && sc[tid] > 0)
            atomicAdd(&g_counts[tid], sc[tid]);

        if (tid == 0) {
            __threadfence();
            isLast = (atomicAdd(&g_done, 1) == HIST_BLKS - 1);
        }
        __syncthreads();
        if (!isLast) return;

        int* seg = (int*)sW1;            // NG+1 ints
        int* cnt = seg + NG + 1;         // NG ints
        if (tid == 0) {
            int blk = 0;
            for (int g = 0; g < NG; g++) {
                seg[g] = blk;
                int c = g_counts[g];
                cnt[g] = c;
                g_cursor[g] = blk * TILE;
                g_counts[g] = 0;         // self-reset for next graph replay
                blk += (c + TILE - 1) / TILE;
            }
            seg[NG] = blk;
            g_done = 0;                  // self-reset
        }
        __syncthreads();
        int total = seg[NG];
        for (int bb = tid; bb < MAXBLK; bb += blockDim.x) {
            int info = -1;
            if (bb < total) {
                int g = 0;
                for (int q = 1; q < NG; q++)
                    if (bb >= seg[q]) g = q;
                int rem = cnt[g] - (bb - seg[g]) * TILE;
                int valid = rem < TILE ? rem : TILE;
                info = g | (valid << 8);
            }
            g_blk_info[bb] = info;
        }
    } else {
        // ---- weight combine (R10-proven body)
        int q = b - (RTE_BLKS + HIST_BLKS);  // 0..511
        int which = q >> 8;                  // 0 = att, 1 = msg
        int rem = q & 255;
        int g = rem >> 3, h = rem & 7;
        int t = g >> 3, et = g & 7;

        const float* W1 = (which ? V_W : K_W) + t * 16384 + h * 16 * 128;
        const float* W2 = (which ? Wmsg : Watt) + et * 256;
        const float* b1 = (which ? V_b : K_b) + t * 128 + h * 16;

#pragma unroll
        for (int it = 0; it < 8; it++) sW1[tid + it * 256] = W1[tid + it * 256];
        sW2[tid & 255] = W2[tid & 255];
        if (tid < 16) sB1[tid] = b1[tid];
        __syncthreads();

        float sc2 = which ? 1.0f : mu[et * NH + h] * 0.25f;
        int i = tid & 127;
        int half = tid >> 7;
        __half* dstW = (which ? g_Bmsg : g_Batt) + g * 16384 + h * 16 * 128;
        float* dstB = (which ? g_bias_msg : g_bias_att) + g * 128 + h * 16;

#pragma unroll
        for (int jj = 0; jj < 8; jj++) {
            int o = jj * 2 + half;
            const float* w2 = sW2 + o * 16;
            float acc = 0.f;
#pragma unroll
            for (int k = 0; k < 16; k++) acc += w2[k] * sW1[k * 128 + i];
            dstW[o * 128 + i] = __float2half_rn(acc * sc2);
            if (i == 0) {
                float bacc = 0.f;
#pragma unroll
                for (int k = 0; k < 16; k++) bacc += w2[k] * sB1[k];
                dstB[o] = bacc * sc2;
            }
        }
    }
}

// scatter v2: 2 edges/thread, 256 blocks; block-aggregated global atomics
__global__ void k_scatter(const int* __restrict__ etype, const int* __restrict__ tau) {
    __shared__ int lcount[NG];
    __shared__ int lbase[NG];
    int tid = threadIdx.x;
    if (tid < NG) lcount[tid] = 0;
    __syncthreads();
    int i0 = blockIdx.x * 512 + tid;
    int i1 = i0 + 256;
    int ga = tau[i0] * 8 + etype[i0];
    int gb = tau[i1] * 8 + etype[i1];
    int ra = atomicAdd(&lcount[ga], 1);
    int rb = atomicAdd(&lcount[gb], 1);
    __syncthreads();
    if (tid < NG && lcount[tid] > 0)
        lbase[tid] = atomicAdd(&g_cursor[tid], lcount[tid]);
    __syncthreads();
    g_perm[lbase[ga] + ra] = i0;
    g_perm[lbase[gb] + rb] = i1;
}

// ---------------- main kernel (byte-identical to R10) ----------------
#define TILE_B  (TILE * 272)           /* 34816 bytes per padded fp16 tile */
#define SM_A    0
#define SM_B    TILE_B
#define DYN_SMEM (2 * TILE_B)          /* 69632 = exactly 128 x 136 floats */
#define MSTRIDE 136                    /* fp32 M-tile row stride (floats) */

__global__ __launch_bounds__(256, 3) void k_main(
    const float* __restrict__ h_s, const float* __restrict__ Q_t,
    const int* __restrict__ dtv, float* __restrict__ out) {
    extern __shared__ char dyn[];
    __shared__ int   sm_perm[TILE];
    __shared__ float sBa[OUTS];
    __shared__ float sBm[OUTS];

    int b = blockIdx.x;
    int info = g_blk_info[b];
    if (info < 0) return;
    int g = info & 31;
    int valid = info >> 8;

    int tid = threadIdx.x;
    int lane = tid & 31;
    int w = tid >> 5;
    int wr = w >> 2, wc = w & 3;
    int R0 = wr * 64, C0 = wc * 32;
    uint32_t sb = smem_u32(dyn);

    // ---- 1) att weight tile via cp.async (latency hidden behind A build)
    {
        const uint4* s0 = (const uint4*)(g_Batt + g * 16384);
#pragma unroll
        for (int it = 0; it < 8; it++) {
            int idx = tid + it * 256;
            int n = idx >> 4, kc = idx & 15;
            cp_async16(sb + SM_B + (uint32_t)(n * 272 + kc * 16), s0 + idx);
        }
        cp_async_commit();
    }

    // ---- 2) per-block constants
    if (tid < TILE) {
        sm_perm[tid] = (tid < valid) ? g_perm[b * TILE + tid] : -1;
        sBa[tid] = g_bias_att[g * 128 + tid];
        sBm[tid] = g_bias_msg[g * 128 + tid];
    }

    // ---- 3) build A tile (fp16) with coalesced h_s reads: warp handles 2 rows
    {
        int rowInWarp = lane >> 4;           // 0 or 1
        int c16 = lane & 15;                 // float4 index within half-row
#pragma unroll
        for (int rb = 0; rb < 8; rb++) {
            int row = rb * 16 + w * 2 + rowInWarp;
            int p = (row < valid) ? g_perm[b * TILE + row] : -1;
            const float4* hs4 = (const float4*)(h_s + (size_t)(p < 0 ? 0 : p) * 128);
            int d = (p >= 0) ? dtv[p] : 0;
            const float4* rt4 = (const float4*)(g_rte + d * 128);
            char* smA = dyn + SM_A + row * 272;
#pragma unroll
            for (int j = 0; j < 2; j++) {
                int c4 = c16 + 16 * j;       // 0..31
                float v0 = 0.f, v1 = 0.f, v2 = 0.f, v3 = 0.f;
                if (p >= 0) {
                    float4 hv = hs4[c4];
                    float4 rv = rt4[c4];
                    v0 = hv.x + rv.x; v1 = hv.y + rv.y;
                    v2 = hv.z + rv.z; v3 = hv.w + rv.w;
                }
                __half2 h01 = __floats2half2_rn(v0, v1);
                __half2 h23 = __floats2half2_rn(v2, v3);
                uint2 pk;
                pk.x = *reinterpret_cast<unsigned*>(&h01);
                pk.y = *reinterpret_cast<unsigned*>(&h23);
                *(uint2*)(smA + c4 * 8) = pk;
            }
        }
    }
    cp_async_wait0();
    __syncthreads();

    uint32_t aB = sb + SM_A;
    uint32_t bB = sb + SM_B;
    uint32_t aOff = (uint32_t)((R0 + (lane & 15)) * 272 + (lane >> 4) * 16);
    uint32_t bOff4 = (uint32_t)((C0 + (lane & 7) + ((lane >> 4) & 1) * 8) * 272 +
                                ((lane >> 3) & 1) * 16);
    int q4 = lane & 3, rquad = lane >> 2;

    // =================== phase 0: attention ===================
    float hsum[4][2][2];
#pragma unroll
    for (int mt = 0; mt < 4; mt++)
#pragma unroll
        for (int rf = 0; rf < 2; rf++)
#pragma unroll
            for (int hl = 0; hl < 2; hl++) hsum[mt][rf][hl] = 0.f;

#pragma unroll
    for (int nh = 0; nh < 2; nh++) {
        float acc[4][2][4];
#pragma unroll
        for (int mt = 0; mt < 4; mt++)
#pragma unroll
            for (int ntl = 0; ntl < 2; ntl++)
#pragma unroll
                for (int v = 0; v < 4; v++) acc[mt][ntl][v] = 0.f;
#pragma unroll
        for (int k = 0; k < 8; k++) {
            uint32_t kb = (uint32_t)(k * 32);
            uint32_t bf[4];
            ldmx4(bf, bB + bOff4 + nh * 16 * 272 + kb);
#pragma unroll
            for (int mt = 0; mt < 4; mt++) {
                uint32_t af[4];
                ldmx4(af, aB + aOff + mt * 16 * 272 + kb);
                mma16816(acc[mt][0], af, bf);
                mma16816(acc[mt][1], af, bf + 2);
            }
        }
#pragma unroll
        for (int mt = 0; mt < 4; mt++) {
            int p1 = sm_perm[R0 + mt * 16 + rquad];
            int p2 = sm_perm[R0 + mt * 16 + rquad + 8];
            const float* q1base = Q_t + (size_t)(p1 < 0 ? 0 : p1) * 128;
            const float* q2base = Q_t + (size_t)(p2 < 0 ? 0 : p2) * 128;
#pragma unroll
            for (int ntl = 0; ntl < 2; ntl++) {
                int col = C0 + nh * 16 + ntl * 8 + q4 * 2;
                float b0 = sBa[col], b1 = sBa[col + 1];
                float2 q1 = __ldg((const float2*)(q1base + col));
                float2 q2 = __ldg((const float2*)(q2base + col));
                hsum[mt][0][nh] += (acc[mt][ntl][0] + b0) * q1.x +
                                   (acc[mt][ntl][1] + b1) * q1.y;
                hsum[mt][1][nh] += (acc[mt][ntl][2] + b0) * q2.x +
                                   (acc[mt][ntl][3] + b1) * q2.y;
            }
        }
    }
    __syncthreads();   // all B(att) reads done -> safe to overwrite

    // ---- kick off msg weight tile load; hidden under att reduce/stores
    {
        const uint4* s1 = (const uint4*)(g_Bmsg + g * 16384);
#pragma unroll
        for (int it = 0; it < 8; it++) {
            int idx = tid + it * 256;
            int n = idx >> 4, kc = idx & 15;
            cp_async16(sb + SM_B + (uint32_t)(n * 272 + kc * 16), s1 + idx);
        }
        cp_async_commit();
    }

    // att reduce + store (mu/4 folded into weights+bias at setup)
#pragma unroll
    for (int mt = 0; mt < 4; mt++)
#pragma unroll
        for (int rf = 0; rf < 2; rf++)
#pragma unroll
            for (int hl = 0; hl < 2; hl++) {
                float v = hsum[mt][rf][hl];
                v += __shfl_xor_sync(0xffffffffu, v, 1);
                v += __shfl_xor_sync(0xffffffffu, v, 2);
                if (q4 == 0) {
                    int p = sm_perm[R0 + mt * 16 + rf * 8 + rquad];
                    if (p >= 0) {
                        int h = wc * 2 + hl;
                        out[(size_t)p * 8 + h] = v;
                    }
                }
            }

    cp_async_wait0();
    __syncthreads();

    // =================== phase 1: messages ===================
    float accm[2][4][2][4];   // [nh][mt][ntl][v]
#pragma unroll
    for (int nh = 0; nh < 2; nh++) {
#pragma unroll
        for (int mt = 0; mt < 4; mt++)
#pragma unroll
            for (int ntl = 0; ntl < 2; ntl++)
#pragma unroll
                for (int v = 0; v < 4; v++) accm[nh][mt][ntl][v] = 0.f;
#pragma unroll
        for (int k = 0; k < 8; k++) {
            uint32_t kb = (uint32_t)(k * 32);
            uint32_t bf[4];
            ldmx4(bf, bB + bOff4 + nh * 16 * 272 + kb);
#pragma unroll
            for (int mt = 0; mt < 4; mt++) {
                uint32_t af[4];
                ldmx4(af, aB + aOff + mt * 16 * 272 + kb);
                mma16816(accm[nh][mt][0], af, bf);
                mma16816(accm[nh][mt][1], af, bf + 2);
            }
        }
    }
    __syncthreads();   // all A/B reads done -> overlay M tile

    // STS: acc (+bias) -> fp32 M tile (stride MSTRIDE floats)
    {
        float* mt32 = (float*)dyn;
#pragma unroll
        for (int nh = 0; nh < 2; nh++)
#pragma unroll
            for (int mt = 0; mt < 4; mt++) {
                int r1 = R0 + mt * 16 + rquad;
#pragma unroll
                for (int ntl = 0; ntl < 2; ntl++) {
                    int col = C0 + nh * 16 + ntl * 8 + q4 * 2;
                    float b0 = sBm[col], b1 = sBm[col + 1];
                    *(float2*)(mt32 + r1 * MSTRIDE + col) =
                        make_float2(accm[nh][mt][ntl][0] + b0,
                                    accm[nh][mt][ntl][1] + b1);
                    *(float2*)(mt32 + (r1 + 8) * MSTRIDE + col) =
                        make_float2(accm[nh][mt][ntl][2] + b0,
                                    accm[nh][mt][ntl][3] + b1);
                }
            }
    }
    __syncthreads();

    // coalesced streaming STG: warp per 2 rows, full 512B lines
    {
        const float* mt32 = (const float*)dyn;
        float* mout = out + (size_t)E_EDGES * 8;
        int rowInWarp = lane >> 4;
        int c16 = lane & 15;
#pragma unroll
        for (int rb = 0; rb < 8; rb++) {
            int row = rb * 16 + w * 2 + rowInWarp;
            int p = sm_perm[row];
            if (p >= 0) {
                float* dst = mout + (size_t)p * 128;
                const float* src = mt32 + row * MSTRIDE;
#pragma unroll
                for (int j = 0; j < 2; j++) {
                    int c4 = c16 + 16 * j;
                    float4 v = *(const float4*)(src + c4 * 4);
                    stg_cs_128(dst + c4 * 4, v);
                }
            }
        }
    }
}

// ---------------- launch ----------------
extern "C" void kernel_launch(void* const* d_in, const int* in_sizes, int n_in,
                              void* d_out, int out_size) {
    const int*   etype = (const int*)d_in[0];
    const int*   tau   = (const int*)d_in[1];
    const float* h_s   = (const float*)d_in[2];
    const float* Q_t   = (const float*)d_in[3];
    const int*   dtv   = (const int*)d_in[4];
    const float* emb   = (const float*)d_in[5];
    const float* linW  = (const float*)d_in[6];
    const float* linb  = (const float*)d_in[7];
    const float* K_W   = (const float*)d_in[8];
    const float* K_b   = (const float*)d_in[9];
    const float* V_W   = (const float*)d_in[10];
    const float* V_b   = (const float*)d_in[11];
    const float* Watt  = (const float*)d_in[12];
    const float* Wmsg  = (const float*)d_in[13];
    const float* mu    = (const float*)d_in[14];
    float* out = (float*)d_out;

    cudaFuncSetAttribute(k_main, cudaFuncAttributeMaxDynamicSharedMemorySize, DYN_SMEM);

    k_setup<<<SETUP_GRID, 256>>>(emb, linW, linb, etype, tau,
                                 K_W, K_b, V_W, V_b, Watt, Wmsg, mu);
    k_scatter<<<E_EDGES / 512, 256>>>(etype, tau);
    k_main<<<MAXBLK, 256, DYN_SMEM>>>(h_s, Q_t, dtv, out);
}

// round 12
// speedup vs baseline: 1.0582x; 1.0582x over previous
#include <cuda_runtime.h>
#include <cuda_fp16.h>
#include <cstdint>

#define E_EDGES 131072
#define INS 128
#define OUTS 128
#define NH 8
#define NG 32          /* tau(4) x etype(8) combined groups */
#define ML 240
#define TILE 128
#define MAXBLK (E_EDGES / TILE + NG)   /* 1056 */
#define HIST_BLKS (E_EDGES / 256)      /* 512 */
#define RTE_ROWS 8
#define RTE_BLKS (ML / RTE_ROWS)       /* 30 */
#define RTE_SMEM ((128 * 129 + RTE_ROWS * 128) * 4)   /* 70144 B */

// ---------------- device scratch ----------------
__device__ int   g_perm[MAXBLK * TILE];
__device__ int   g_counts[NG];
__device__ int   g_cursor[NG];
__device__ int   g_done;               // last-block flag (self-resetting)
__device__ int   g_blk_info[MAXBLK];   // g | (valid<<8), or -1
__device__ float g_rte[ML * INS];
__device__ __half g_Batt[NG * 16384];  // combined [g][n][k] fp16 (mu/4 folded)
__device__ __half g_Bmsg[NG * 16384];
__device__ float g_bias_att[NG * OUTS];
__device__ float g_bias_msg[NG * OUTS];

// ---------------- helpers ----------------
__device__ __forceinline__ uint32_t smem_u32(const void* p) {
    uint32_t a;
    asm("{ .reg .u64 t; cvta.to.shared.u64 t, %1; cvt.u32.u64 %0, t; }"
        : "=r"(a) : "l"(p));
    return a;
}
__device__ __forceinline__ void ldmx4(uint32_t* r, uint32_t addr) {
    asm volatile("ldmatrix.sync.aligned.m8n8.x4.shared.b16 {%0,%1,%2,%3}, [%4];"
                 : "=r"(r[0]), "=r"(r[1]), "=r"(r[2]), "=r"(r[3]) : "r"(addr));
}
__device__ __forceinline__ void mma16816(float* c, const uint32_t* a, const uint32_t* b) {
    asm volatile(
        "mma.sync.aligned.m16n8k16.row.col.f32.f16.f16.f32 "
        "{%0,%1,%2,%3}, {%4,%5,%6,%7}, {%8,%9}, {%0,%1,%2,%3};"
        : "+f"(c[0]), "+f"(c[1]), "+f"(c[2]), "+f"(c[3])
        : "r"(a[0]), "r"(a[1]), "r"(a[2]), "r"(a[3]), "r"(b[0]), "r"(b[1]));
}
__device__ __forceinline__ void cp_async16(uint32_t saddr, const void* gaddr) {
    asm volatile("cp.async.cg.shared.global [%0], [%1], 16;"
                 :: "r"(saddr), "l"(gaddr));
}
__device__ __forceinline__ void cp_async_commit() {
    asm volatile("cp.async.commit_group;");
}
__device__ __forceinline__ void cp_async_wait0() {
    asm volatile("cp.async.wait_group 0;");
}
__device__ __forceinline__ void stg_cs_128(float* p, float4 v) {
    asm volatile("st.global.cs.v4.f32 [%0], {%1,%2,%3,%4};"
                 :: "l"(p), "f"(v.x), "f"(v.y), "f"(v.z), "f"(v.w) : "memory");
}

// ---------------- setup kernels ----------------
// RTE v2: smem-staged linW (coalesced loads, conflict-free reads).
// 30 blocks x 8 dt-rows; also zeros g_counts (block 0).
__global__ void k_rte(const float* __restrict__ emb,
                      const float* __restrict__ linW,
                      const float* __restrict__ linb) {
    extern __shared__ float s[];
    float* sW = s;                       // [128][129]
    float* sE = s + 128 * 129;           // [RTE_ROWS][128]
    int tid = threadIdx.x;
    int b = blockIdx.x;
    if (b == 0 && tid < NG) g_counts[tid] = 0;

    for (int idx = tid; idx < 128 * 128; idx += 256) {
        int o = idx >> 7, i = idx & 127;
        sW[o * 129 + i] = linW[idx];     // coalesced global read
    }
    int d0 = b * RTE_ROWS;
    for (int idx = tid; idx < RTE_ROWS * 128; idx += 256)
        sE[idx] = emb[d0 * 128 + idx];
    __syncthreads();

    int o = tid & 127;
    int half = tid >> 7;
    float bias = linb[o];
    const float* w = sW + o * 129;
    for (int dd = half; dd < RTE_ROWS; dd += 2) {
        const float* e = sE + dd * 128;
        float acc = bias;
#pragma unroll 8
        for (int i = 0; i < 128; i++) acc += e[i] * w[i];
        g_rte[(d0 + dd) * 128 + o] = acc;
    }
}

// histogram + (last block) offsets, fused (R10-proven)
__global__ void k_hist(const int* __restrict__ etype, const int* __restrict__ tau) {
    __shared__ int sc[NG];
    __shared__ int isLast;
    int tid = threadIdx.x;
    if (tid < NG) sc[tid] = 0;
    __syncthreads();
    int i = blockIdx.x * blockDim.x + tid;
    atomicAdd(&sc[tau[i] * 8 + etype[i]], 1);
    __syncthreads();
    if (tid < NG && sc[tid] > 0)
        atomicAdd(&g_counts[tid], sc[tid]);

    if (tid == 0) {
        __threadfence();
        isLast = (atomicAdd(&g_done, 1) == gridDim.x - 1);
    }
    __syncthreads();
    if (!isLast) return;

    __shared__ int seg[NG + 1];
    __shared__ int cnt[NG];
    if (tid == 0) {
        int blk = 0;
        for (int g = 0; g < NG; g++) {
            seg[g] = blk;
            int c = g_counts[g];
            cnt[g] = c;
            g_cursor[g] = blk * TILE;
            blk += (c + TILE - 1) / TILE;
        }
        seg[NG] = blk;
        g_done = 0;   // reset for next graph replay
    }
    __syncthreads();
    int total = seg[NG];
    for (int b = tid; b < MAXBLK; b += blockDim.x) {
        int info = -1;
        if (b < total) {
            int g = 0;
            for (int q = 1; q < NG; q++)
                if (b >= seg[q]) g = q;
            int rem = cnt[g] - (b - seg[g]) * TILE;
            int valid = rem < TILE ? rem : TILE;
            info = g | (valid << 8);
        }
        g_blk_info[b] = info;
    }
}

__global__ void k_scatter(const int* __restrict__ etype, const int* __restrict__ tau) {
    __shared__ int lcount[NG];
    __shared__ int lbase[NG];
    int tid = threadIdx.x;
    if (tid < NG) lcount[tid] = 0;
    __syncthreads();
    int i = blockIdx.x * blockDim.x + tid;
    int g = tau[i] * 8 + etype[i];
    int rank = atomicAdd(&lcount[g], 1);
    __syncthreads();
    if (tid < NG && lcount[tid] > 0)
        lbase[tid] = atomicAdd(&g_cursor[tid], lcount[tid]);
    __syncthreads();
    g_perm[lbase[g] + rank] = i;
}

// combined weights v2 (R10-proven): grid (h=8, g=32, which=2), 8.5KB smem staged.
__global__ void k_wcomb(const float* __restrict__ K_W, const float* __restrict__ K_b,
                        const float* __restrict__ V_W, const float* __restrict__ V_b,
                        const float* __restrict__ Watt, const float* __restrict__ Wmsg,
                        const float* __restrict__ mu) {
    __shared__ float sW1[16 * 128];
    __shared__ float sW2[256];
    __shared__ float sB1[16];

    int h = blockIdx.x;               // 0..7
    int g = blockIdx.y;               // 0..31
    int which = blockIdx.z;           // 0 = att, 1 = msg
    int t = g >> 3, et = g & 7;
    int tid = threadIdx.x;

    const float* W1 = (which ? V_W : K_W) + t * 16384 + h * 16 * 128;
    const float* W2 = (which ? Wmsg : Watt) + et * 256;
    const float* b1 = (which ? V_b : K_b) + t * 128 + h * 16;

#pragma unroll
    for (int it = 0; it < 8; it++) sW1[tid + it * 256] = W1[tid + it * 256];
    if (tid < 256) sW2[tid] = W2[tid];
    if (tid < 16) sB1[tid] = b1[tid];
    __syncthreads();

    float sc = which ? 1.0f : mu[et * NH + h] * 0.25f;
    int i = tid & 127;
    int half = tid >> 7;
    __half* dstW = (which ? g_Bmsg : g_Batt) + g * 16384 + h * 16 * 128;
    float* dstB = (which ? g_bias_msg : g_bias_att) + g * 128 + h * 16;

#pragma unroll
    for (int jj = 0; jj < 8; jj++) {
        int o = jj * 2 + half;
        const float* w2 = sW2 + o * 16;
        float acc = 0.f;
#pragma unroll
        for (int k = 0; k < 16; k++) acc += w2[k] * sW1[k * 128 + i];
        dstW[o * 128 + i] = __float2half_rn(acc * sc);
        if (i == 0) {
            float bacc = 0.f;
#pragma unroll
            for (int k = 0; k < 16; k++) bacc += w2[k] * sB1[k];
            dstB[o] = bacc * sc;
        }
    }
}

// ---------------- main kernel (byte-identical to R10) ----------------
#define TILE_B  (TILE * 272)           /* 34816 bytes per padded fp16 tile */
#define SM_A    0
#define SM_B    TILE_B
#define DYN_SMEM (2 * TILE_B)          /* 69632 = exactly 128 x 136 floats */
#define MSTRIDE 136                    /* fp32 M-tile row stride (floats) */

__global__ __launch_bounds__(256, 3) void k_main(
    const float* __restrict__ h_s, const float* __restrict__ Q_t,
    const int* __restrict__ dtv, float* __restrict__ out) {
    extern __shared__ char dyn[];
    __shared__ int   sm_perm[TILE];
    __shared__ float sBa[OUTS];
    __shared__ float sBm[OUTS];

    int b = blockIdx.x;
    int info = g_blk_info[b];
    if (info < 0) return;
    int g = info & 31;
    int valid = info >> 8;

    int tid = threadIdx.x;
    int lane = tid & 31;
    int w = tid >> 5;
    int wr = w >> 2, wc = w & 3;
    int R0 = wr * 64, C0 = wc * 32;
    uint32_t sb = smem_u32(dyn);

    // ---- 1) att weight tile via cp.async (latency hidden behind A build)
    {
        const uint4* s0 = (const uint4*)(g_Batt + g * 16384);
#pragma unroll
        for (int it = 0; it < 8; it++) {
            int idx = tid + it * 256;
            int n = idx >> 4, kc = idx & 15;
            cp_async16(sb + SM_B + (uint32_t)(n * 272 + kc * 16), s0 + idx);
        }
        cp_async_commit();
    }

    // ---- 2) per-block constants
    if (tid < TILE) {
        sm_perm[tid] = (tid < valid) ? g_perm[b * TILE + tid] : -1;
        sBa[tid] = g_bias_att[g * 128 + tid];
        sBm[tid] = g_bias_msg[g * 128 + tid];
    }

    // ---- 3) build A tile (fp16) with coalesced h_s reads: warp handles 2 rows
    {
        int rowInWarp = lane >> 4;           // 0 or 1
        int c16 = lane & 15;                 // float4 index within half-row
#pragma unroll
        for (int rb = 0; rb < 8; rb++) {
            int row = rb * 16 + w * 2 + rowInWarp;
            int p = (row < valid) ? g_perm[b * TILE + row] : -1;
            const float4* hs4 = (const float4*)(h_s + (size_t)(p < 0 ? 0 : p) * 128);
            int d = (p >= 0) ? dtv[p] : 0;
            const float4* rt4 = (const float4*)(g_rte + d * 128);
            char* smA = dyn + SM_A + row * 272;
#pragma unroll
            for (int j = 0; j < 2; j++) {
                int c4 = c16 + 16 * j;       // 0..31
                float v0 = 0.f, v1 = 0.f, v2 = 0.f, v3 = 0.f;
                if (p >= 0) {
                    float4 hv = hs4[c4];
                    float4 rv = rt4[c4];
                    v0 = hv.x + rv.x; v1 = hv.y + rv.y;
                    v2 = hv.z + rv.z; v3 = hv.w + rv.w;
                }
                __half2 h01 = __floats2half2_rn(v0, v1);
                __half2 h23 = __floats2half2_rn(v2, v3);
                uint2 pk;
                pk.x = *reinterpret_cast<unsigned*>(&h01);
                pk.y = *reinterpret_cast<unsigned*>(&h23);
                *(uint2*)(smA + c4 * 8) = pk;
            }
        }
    }
    cp_async_wait0();
    __syncthreads();

    uint32_t aB = sb + SM_A;
    uint32_t bB = sb + SM_B;
    uint32_t aOff = (uint32_t)((R0 + (lane & 15)) * 272 + (lane >> 4) * 16);
    uint32_t bOff4 = (uint32_t)((C0 + (lane & 7) + ((lane >> 4) & 1) * 8) * 272 +
                                ((lane >> 3) & 1) * 16);
    int q4 = lane & 3, rquad = lane >> 2;

    // =================== phase 0: attention ===================
    float hsum[4][2][2];
#pragma unroll
    for (int mt = 0; mt < 4; mt++)
#pragma unroll
        for (int rf = 0; rf < 2; rf++)
#pragma unroll
            for (int hl = 0; hl < 2; hl++) hsum[mt][rf][hl] = 0.f;

#pragma unroll
    for (int nh = 0; nh < 2; nh++) {
        float acc[4][2][4];
#pragma unroll
        for (int mt = 0; mt < 4; mt++)
#pragma unroll
            for (int ntl = 0; ntl < 2; ntl++)
#pragma unroll
                for (int v = 0; v < 4; v++) acc[mt][ntl][v] = 0.f;
#pragma unroll
        for (int k = 0; k < 8; k++) {
            uint32_t kb = (uint32_t)(k * 32);
            uint32_t bf[4];
            ldmx4(bf, bB + bOff4 + nh * 16 * 272 + kb);
#pragma unroll
            for (int mt = 0; mt < 4; mt++) {
                uint32_t af[4];
                ldmx4(af, aB + aOff + mt * 16 * 272 + kb);
                mma16816(acc[mt][0], af, bf);
                mma16816(acc[mt][1], af, bf + 2);
            }
        }
#pragma unroll
        for (int mt = 0; mt < 4; mt++) {
            int p1 = sm_perm[R0 + mt * 16 + rquad];
            int p2 = sm_perm[R0 + mt * 16 + rquad + 8];
            const float* q1base = Q_t + (size_t)(p1 < 0 ? 0 : p1) * 128;
            const float* q2base = Q_t + (size_t)(p2 < 0 ? 0 : p2) * 128;
#pragma unroll
            for (int ntl = 0; ntl < 2; ntl++) {
                int col = C0 + nh * 16 + ntl * 8 + q4 * 2;
                float b0 = sBa[col], b1 = sBa[col + 1];
                float2 q1 = __ldg((const float2*)(q1base + col));
                float2 q2 = __ldg((const float2*)(q2base + col));
                hsum[mt][0][nh] += (acc[mt][ntl][0] + b0) * q1.x +
                                   (acc[mt][ntl][1] + b1) * q1.y;
                hsum[mt][1][nh] += (acc[mt][ntl][2] + b0) * q2.x +
                                   (acc[mt][ntl][3] + b1) * q2.y;
            }
        }
    }
    __syncthreads();   // all B(att) reads done -> safe to overwrite

    // ---- kick off msg weight tile load; hidden under att reduce/stores
    {
        const uint4* s1 = (const uint4*)(g_Bmsg + g * 16384);
#pragma unroll
        for (int it = 0; it < 8; it++) {
            int idx = tid + it * 256;
            int n = idx >> 4, kc = idx & 15;
            cp_async16(sb + SM_B + (uint32_t)(n * 272 + kc * 16), s1 + idx);
        }
        cp_async_commit();
    }

    // att reduce + store (mu/4 folded into weights+bias at setup)
#pragma unroll
    for (int mt = 0; mt < 4; mt++)
#pragma unroll
        for (int rf = 0; rf < 2; rf++)
#pragma unroll
            for (int hl = 0; hl < 2; hl++) {
                float v = hsum[mt][rf][hl];
                v += __shfl_xor_sync(0xffffffffu, v, 1);
                v += __shfl_xor_sync(0xffffffffu, v, 2);
                if (q4 == 0) {
                    int p = sm_perm[R0 + mt * 16 + rf * 8 + rquad];
                    if (p >= 0) {
                        int h = wc * 2 + hl;
                        out[(size_t)p * 8 + h] = v;
                    }
                }
            }

    cp_async_wait0();
    __syncthreads();

    // =================== phase 1: messages ===================
    float accm[2][4][2][4];   // [nh][mt][ntl][v]
#pragma unroll
    for (int nh = 0; nh < 2; nh++) {
#pragma unroll
        for (int mt = 0; mt < 4; mt++)
#pragma unroll
            for (int ntl = 0; ntl < 2; ntl++)
#pragma unroll
                for (int v = 0; v < 4; v++) accm[nh][mt][ntl][v] = 0.f;
#pragma unroll
        for (int k = 0; k < 8; k++) {
            uint32_t kb = (uint32_t)(k * 32);
            uint32_t bf[4];
            ldmx4(bf, bB + bOff4 + nh * 16 * 272 + kb);
#pragma unroll
            for (int mt = 0; mt < 4; mt++) {
                uint32_t af[4];
                ldmx4(af, aB + aOff + mt * 16 * 272 + kb);
                mma16816(accm[nh][mt][0], af, bf);
                mma16816(accm[nh][mt][1], af, bf + 2);
            }
        }
    }
    __syncthreads();   // all A/B reads done -> overlay M tile

    // STS: acc (+bias) -> fp32 M tile (stride MSTRIDE floats)
    {
        float* mt32 = (float*)dyn;
#pragma unroll
        for (int nh = 0; nh < 2; nh++)
#pragma unroll
            for (int mt = 0; mt < 4; mt++) {
                int r1 = R0 + mt * 16 + rquad;
#pragma unroll
                for (int ntl = 0; ntl < 2; ntl++) {
                    int col = C0 + nh * 16 + ntl * 8 + q4 * 2;
                    float b0 = sBm[col], b1 = sBm[col + 1];
                    *(float2*)(mt32 + r1 * MSTRIDE + col) =
                        make_float2(accm[nh][mt][ntl][0] + b0,
                                    accm[nh][mt][ntl][1] + b1);
                    *(float2*)(mt32 + (r1 + 8) * MSTRIDE + col) =
                        make_float2(accm[nh][mt][ntl][2] + b0,
                                    accm[nh][mt][ntl][3] + b1);
                }
            }
    }
    __syncthreads();

    // coalesced streaming STG: warp per 2 rows, full 512B lines
    {
        const float* mt32 = (const float*)dyn;
        float* mout = out + (size_t)E_EDGES * 8;
        int rowInWarp = lane >> 4;
        int c16 = lane & 15;
#pragma unroll
        for (int rb = 0; rb < 8; rb++) {
            int row = rb * 16 + w * 2 + rowInWarp;
            int p = sm_perm[row];
            if (p >= 0) {
                float* dst = mout + (size_t)p * 128;
                const float* src = mt32 + row * MSTRIDE;
#pragma unroll
                for (int j = 0; j < 2; j++) {
                    int c4 = c16 + 16 * j;
                    float4 v = *(const float4*)(src + c4 * 4);
                    stg_cs_128(dst + c4 * 4, v);
                }
            }
        }
    }
}

// ---------------- launch ----------------
extern "C" void kernel_launch(void* const* d_in, const int* in_sizes, int n_in,
                              void* d_out, int out_size) {
    const int*   etype = (const int*)d_in[0];
    const int*   tau   = (const int*)d_in[1];
    const float* h_s   = (const float*)d_in[2];
    const float* Q_t   = (const float*)d_in[3];
    const int*   dtv   = (const int*)d_in[4];
    const float* emb   = (const float*)d_in[5];
    const float* linW  = (const float*)d_in[6];
    const float* linb  = (const float*)d_in[7];
    const float* K_W   = (const float*)d_in[8];
    const float* K_b   = (const float*)d_in[9];
    const float* V_W   = (const float*)d_in[10];
    const float* V_b   = (const float*)d_in[11];
    const float* Watt  = (const float*)d_in[12];
    const float* Wmsg  = (const float*)d_in[13];
    const float* mu    = (const float*)d_in[14];
    float* out = (float*)d_out;

    cudaFuncSetAttribute(k_main, cudaFuncAttributeMaxDynamicSharedMemorySize, DYN_SMEM);
    cudaFuncSetAttribute(k_rte, cudaFuncAttributeMaxDynamicSharedMemorySize, RTE_SMEM);

    k_rte<<<RTE_BLKS, 256, RTE_SMEM>>>(emb, linW, linb);   // also zeros g_counts
    k_hist<<<HIST_BLKS, 256>>>(etype, tau);                // + fused offsets
    k_scatter<<<E_EDGES / 256, 256>>>(etype, tau);
    k_wcomb<<<dim3(NH, NG, 2), 256>>>(K_W, K_b, V_W, V_b, Watt, Wmsg, mu);
    k_main<<<MAXBLK, 256, DYN_SMEM>>>(h_s, Q_t, dtv, out);
}

// round 13
// speedup vs baseline: 1.1120x; 1.0508x over previous
#include <cuda_runtime.h>
#include <cuda_fp16.h>
#include <cstdint>

#define E_EDGES 131072
#define INS 128
#define OUTS 128
#define NH 8
#define NG 32          /* tau(4) x etype(8) combined groups */
#define ML 240
#define TILE 128
#define MAXBLK (E_EDGES / TILE + NG)   /* 1056 */

#define HIST_BLKS  512
#define WC_BLKS    512
#define RTE_BLKS   (ML / 8)            /* 30 */
#define SETUP_GRID (HIST_BLKS + WC_BLKS + RTE_BLKS)   /* 1054 */

// ---------------- device scratch ----------------
__device__ int   g_perm[MAXBLK * TILE];
__device__ int   g_counts[NG];         // zero at load; self-zeroed each replay
__device__ int   g_cursor[NG];
__device__ int   g_done;               // zero at load; self-zeroed each replay
__device__ int   g_blk_info[MAXBLK];   // g | (valid<<8), or -1
__device__ float g_rte[ML * INS];
__device__ __half g_Batt[NG * 16384];  // combined [g][n][k] fp16 (mu/4 folded)
__device__ __half g_Bmsg[NG * 16384];
__device__ float g_bias_att[NG * OUTS];
__device__ float g_bias_msg[NG * OUTS];

// ---------------- helpers ----------------
__device__ __forceinline__ uint32_t smem_u32(const void* p) {
    uint32_t a;
    asm("{ .reg .u64 t; cvta.to.shared.u64 t, %1; cvt.u32.u64 %0, t; }"
        : "=r"(a) : "l"(p));
    return a;
}
__device__ __forceinline__ void ldmx4(uint32_t* r, uint32_t addr) {
    asm volatile("ldmatrix.sync.aligned.m8n8.x4.shared.b16 {%0,%1,%2,%3}, [%4];"
                 : "=r"(r[0]), "=r"(r[1]), "=r"(r[2]), "=r"(r[3]) : "r"(addr));
}
__device__ __forceinline__ void mma16816(float* c, const uint32_t* a, const uint32_t* b) {
    asm volatile(
        "mma.sync.aligned.m16n8k16.row.col.f32.f16.f16.f32 "
        "{%0,%1,%2,%3}, {%4,%5,%6,%7}, {%8,%9}, {%0,%1,%2,%3};"
        : "+f"(c[0]), "+f"(c[1]), "+f"(c[2]), "+f"(c[3])
        : "r"(a[0]), "r"(a[1]), "r"(a[2]), "r"(a[3]), "r"(b[0]), "r"(b[1]));
}
__device__ __forceinline__ void cp_async16(uint32_t saddr, const void* gaddr) {
    asm volatile("cp.async.cg.shared.global [%0], [%1], 16;"
                 :: "r"(saddr), "l"(gaddr));
}
__device__ __forceinline__ void cp_async_commit() {
    asm volatile("cp.async.commit_group;");
}
__device__ __forceinline__ void cp_async_wait0() {
    asm volatile("cp.async.wait_group 0;");
}
__device__ __forceinline__ void stg_cs_128(float* p, float4 v) {
    asm volatile("st.global.cs.v4.f32 [%0], {%1,%2,%3,%4};"
                 :: "l"(p), "f"(v.x), "f"(v.y), "f"(v.z), "f"(v.w) : "memory");
}

// ---------------- fused setup: hist(+offsets) | weight-combine | RTE ----------------
// Static smem union sized for the largest role (RTE: 32x129 + 8x128 floats).
#define SBUF_FLOATS (32 * 129 + 8 * 128)   /* 5152 floats = 20608 B */

__global__ void k_setup(const float* __restrict__ emb,
                        const float* __restrict__ linW,
                        const float* __restrict__ linb,
                        const int* __restrict__ etype,
                        const int* __restrict__ tau,
                        const float* __restrict__ K_W, const float* __restrict__ K_b,
                        const float* __restrict__ V_W, const float* __restrict__ V_b,
                        const float* __restrict__ Watt, const float* __restrict__ Wmsg,
                        const float* __restrict__ mu) {
    __shared__ float sbuf[SBUF_FLOATS];
    __shared__ int   sc[NG];
    __shared__ int   seg[NG + 1];
    __shared__ int   cnt[NG];
    __shared__ int   isLast;

    int b = blockIdx.x;
    int tid = threadIdx.x;

    if (b < HIST_BLKS) {
        // ---- histogram; last-done hist block computes offsets (R12-proven)
        if (tid < NG) sc[tid] = 0;
        __syncthreads();
        int i = b * 256 + tid;
        atomicAdd(&sc[tau[i] * 8 + etype[i]], 1);
        __syncthreads();
        if (tid < NG && sc[tid] > 0)
            atomicAdd(&g_counts[tid], sc[tid]);

        if (tid == 0) {
            __threadfence();
            isLast = (atomicAdd(&g_done, 1) == HIST_BLKS - 1);
        }
        __syncthreads();
        if (!isLast) return;

        if (tid == 0) {
            int blk = 0;
            for (int g = 0; g < NG; g++) {
                seg[g] = blk;
                int c = g_counts[g];
                cnt[g] = c;
                g_cursor[g] = blk * TILE;
                g_counts[g] = 0;         // self-reset for next graph replay
                blk += (c + TILE - 1) / TILE;
            }
            seg[NG] = blk;
            g_done = 0;                  // self-reset
        }
        __syncthreads();
        int total = seg[NG];
        for (int bb = tid; bb < MAXBLK; bb += blockDim.x) {
            int info = -1;
            if (bb < total) {
                int g = 0;
                for (int q = 1; q < NG; q++)
                    if (bb >= seg[q]) g = q;
                int rem = cnt[g] - (bb - seg[g]) * TILE;
                int valid = rem < TILE ? rem : TILE;
                info = g | (valid << 8);
            }
            g_blk_info[bb] = info;
        }
    } else if (b < HIST_BLKS + WC_BLKS) {
        // ---- weight combine (R12-proven body)
        float* sW1 = sbuf;               // 16*128
        float* sW2 = sbuf + 16 * 128;    // 256
        float* sB1 = sW2 + 256;          // 16

        int q = b - HIST_BLKS;           // 0..511
        int which = q >> 8;              // 0 = att, 1 = msg
        int rem = q & 255;
        int g = rem >> 3, h = rem & 7;
        int t = g >> 3, et = g & 7;

        const float* W1 = (which ? V_W : K_W) + t * 16384 + h * 16 * 128;
        const float* W2 = (which ? Wmsg : Watt) + et * 256;
        const float* b1 = (which ? V_b : K_b) + t * 128 + h * 16;

#pragma unroll
        for (int it = 0; it < 8; it++) sW1[tid + it * 256] = W1[tid + it * 256];
        sW2[tid & 255] = W2[tid & 255];
        if (tid < 16) sB1[tid] = b1[tid];
        __syncthreads();

        float sc2 = which ? 1.0f : mu[et * NH + h] * 0.25f;
        int i = tid & 127;
        int half = tid >> 7;
        __half* dstW = (which ? g_Bmsg : g_Batt) + g * 16384 + h * 16 * 128;
        float* dstB = (which ? g_bias_msg : g_bias_att) + g * 128 + h * 16;

#pragma unroll
        for (int jj = 0; jj < 8; jj++) {
            int o = jj * 2 + half;
            const float* w2 = sW2 + o * 16;
            float acc = 0.f;
#pragma unroll
            for (int k = 0; k < 16; k++) acc += w2[k] * sW1[k * 128 + i];
            dstW[o * 128 + i] = __float2half_rn(acc * sc2);
            if (i == 0) {
                float bacc = 0.f;
#pragma unroll
                for (int k = 0; k < 16; k++) bacc += w2[k] * sB1[k];
                dstB[o] = bacc * sc2;
            }
        }
    } else {
        // ---- RTE: 8 dt rows per block; linW staged in 4 passes of 32 rows.
        float* sW = sbuf;                // [32][129]
        float* sE = sbuf + 32 * 129;     // [8][128]
        int d0 = (b - HIST_BLKS - WC_BLKS) * 8;

        for (int idx = tid; idx < 8 * 128; idx += 256)
            sE[idx] = emb[d0 * 128 + idx];

        int oLoc = tid & 31;
        int d = tid >> 5;                // 0..7
        const float* e = sE + d * 128;
        const float* w = sW + oLoc * 129;
#pragma unroll
        for (int qp = 0; qp < 4; qp++) {
            __syncthreads();
            for (int idx = tid; idx < 32 * 128; idx += 256) {
                int o = idx >> 7, i = idx & 127;
                sW[o * 129 + i] = linW[(qp * 32 + o) * 128 + i];  // coalesced
            }
            __syncthreads();
            int o = qp * 32 + oLoc;
            float acc = linb[o];
#pragma unroll 8
            for (int i = 0; i < 128; i++) acc += e[i] * w[i];
            g_rte[(d0 + d) * 128 + o] = acc;
        }
    }
}

// scatter (R12-proven)
__global__ void k_scatter(const int* __restrict__ etype, const int* __restrict__ tau) {
    __shared__ int lcount[NG];
    __shared__ int lbase[NG];
    int tid = threadIdx.x;
    if (tid < NG) lcount[tid] = 0;
    __syncthreads();
    int i = blockIdx.x * blockDim.x + tid;
    int g = tau[i] * 8 + etype[i];
    int rank = atomicAdd(&lcount[g], 1);
    __syncthreads();
    if (tid < NG && lcount[tid] > 0)
        lbase[tid] = atomicAdd(&g_cursor[tid], lcount[tid]);
    __syncthreads();
    g_perm[lbase[g] + rank] = i;
}

// ---------------- main kernel (byte-identical to R12) ----------------
#define TILE_B  (TILE * 272)           /* 34816 bytes per padded fp16 tile */
#define SM_A    0
#define SM_B    TILE_B
#define DYN_SMEM (2 * TILE_B)          /* 69632 = exactly 128 x 136 floats */
#define MSTRIDE 136                    /* fp32 M-tile row stride (floats) */

__global__ __launch_bounds__(256, 3) void k_main(
    const float* __restrict__ h_s, const float* __restrict__ Q_t,
    const int* __restrict__ dtv, float* __restrict__ out) {
    extern __shared__ char dyn[];
    __shared__ int   sm_perm[TILE];
    __shared__ float sBa[OUTS];
    __shared__ float sBm[OUTS];

    int b = blockIdx.x;
    int info = g_blk_info[b];
    if (info < 0) return;
    int g = info & 31;
    int valid = info >> 8;

    int tid = threadIdx.x;
    int lane = tid & 31;
    int w = tid >> 5;
    int wr = w >> 2, wc = w & 3;
    int R0 = wr * 64, C0 = wc * 32;
    uint32_t sb = smem_u32(dyn);

    // ---- 1) att weight tile via cp.async (latency hidden behind A build)
    {
        const uint4* s0 = (const uint4*)(g_Batt + g * 16384);
#pragma unroll
        for (int it = 0; it < 8; it++) {
            int idx = tid + it * 256;
            int n = idx >> 4, kc = idx & 15;
            cp_async16(sb + SM_B + (uint32_t)(n * 272 + kc * 16), s0 + idx);
        }
        cp_async_commit();
    }

    // ---- 2) per-block constants
    if (tid < TILE) {
        sm_perm[tid] = (tid < valid) ? g_perm[b * TILE + tid] : -1;
        sBa[tid] = g_bias_att[g * 128 + tid];
        sBm[tid] = g_bias_msg[g * 128 + tid];
    }

    // ---- 3) build A tile (fp16) with coalesced h_s reads: warp handles 2 rows
    {
        int rowInWarp = lane >> 4;           // 0 or 1
        int c16 = lane & 15;                 // float4 index within half-row
#pragma unroll
        for (int rb = 0; rb < 8; rb++) {
            int row = rb * 16 + w * 2 + rowInWarp;
            int p = (row < valid) ? g_perm[b * TILE + row] : -1;
            const float4* hs4 = (const float4*)(h_s + (size_t)(p < 0 ? 0 : p) * 128);
            int d = (p >= 0) ? dtv[p] : 0;
            const float4* rt4 = (const float4*)(g_rte + d * 128);
            char* smA = dyn + SM_A + row * 272;
#pragma unroll
            for (int j = 0; j < 2; j++) {
                int c4 = c16 + 16 * j;       // 0..31
                float v0 = 0.f, v1 = 0.f, v2 = 0.f, v3 = 0.f;
                if (p >= 0) {
                    float4 hv = hs4[c4];
                    float4 rv = rt4[c4];
                    v0 = hv.x + rv.x; v1 = hv.y + rv.y;
                    v2 = hv.z + rv.z; v3 = hv.w + rv.w;
                }
                __half2 h01 = __floats2half2_rn(v0, v1);
                __half2 h23 = __floats2half2_rn(v2, v3);
                uint2 pk;
                pk.x = *reinterpret_cast<unsigned*>(&h01);
                pk.y = *reinterpret_cast<unsigned*>(&h23);
                *(uint2*)(smA + c4 * 8) = pk;
            }
        }
    }
    cp_async_wait0();
    __syncthreads();

    uint32_t aB = sb + SM_A;
    uint32_t bB = sb + SM_B;
    uint32_t aOff = (uint32_t)((R0 + (lane & 15)) * 272 + (lane >> 4) * 16);
    uint32_t bOff4 = (uint32_t)((C0 + (lane & 7) + ((lane >> 4) & 1) * 8) * 272 +
                                ((lane >> 3) & 1) * 16);
    int q4 = lane & 3, rquad = lane >> 2;

    // =================== phase 0: attention ===================
    float hsum[4][2][2];
#pragma unroll
    for (int mt = 0; mt < 4; mt++)
#pragma unroll
        for (int rf = 0; rf < 2; rf++)
#pragma unroll
            for (int hl = 0; hl < 2; hl++) hsum[mt][rf][hl] = 0.f;

#pragma unroll
    for (int nh = 0; nh < 2; nh++) {
        float acc[4][2][4];
#pragma unroll
        for (int mt = 0; mt < 4; mt++)
#pragma unroll
            for (int ntl = 0; ntl < 2; ntl++)
#pragma unroll
                for (int v = 0; v < 4; v++) acc[mt][ntl][v] = 0.f;
#pragma unroll
        for (int k = 0; k < 8; k++) {
            uint32_t kb = (uint32_t)(k * 32);
            uint32_t bf[4];
            ldmx4(bf, bB + bOff4 + nh * 16 * 272 + kb);
#pragma unroll
            for (int mt = 0; mt < 4; mt++) {
                uint32_t af[4];
                ldmx4(af, aB + aOff + mt * 16 * 272 + kb);
                mma16816(acc[mt][0], af, bf);
                mma16816(acc[mt][1], af, bf + 2);
            }
        }
#pragma unroll
        for (int mt = 0; mt < 4; mt++) {
            int p1 = sm_perm[R0 + mt * 16 + rquad];
            int p2 = sm_perm[R0 + mt * 16 + rquad + 8];
            const float* q1base = Q_t + (size_t)(p1 < 0 ? 0 : p1) * 128;
            const float* q2base = Q_t + (size_t)(p2 < 0 ? 0 : p2) * 128;
#pragma unroll
            for (int ntl = 0; ntl < 2; ntl++) {
                int col = C0 + nh * 16 + ntl * 8 + q4 * 2;
                float b0 = sBa[col], b1 = sBa[col + 1];
                float2 q1 = __ldg((const float2*)(q1base + col));
                float2 q2 = __ldg((const float2*)(q2base + col));
                hsum[mt][0][nh] += (acc[mt][ntl][0] + b0) * q1.x +
                                   (acc[mt][ntl][1] + b1) * q1.y;
                hsum[mt][1][nh] += (acc[mt][ntl][2] + b0) * q2.x +
                                   (acc[mt][ntl][3] + b1) * q2.y;
            }
        }
    }
    __syncthreads();   // all B(att) reads done -> safe to overwrite

    // ---- kick off msg weight tile load; hidden under att reduce/stores
    {
        const uint4* s1 = (const uint4*)(g_Bmsg + g * 16384);
#pragma unroll
        for (int it = 0; it < 8; it++) {
            int idx = tid + it * 256;
            int n = idx >> 4, kc = idx & 15;
            cp_async16(sb + SM_B + (uint32_t)(n * 272 + kc * 16), s1 + idx);
        }
        cp_async_commit();
    }

    // att reduce + store (mu/4 folded into weights+bias at setup)
#pragma unroll
    for (int mt = 0; mt < 4; mt++)
#pragma unroll
        for (int rf = 0; rf < 2; rf++)
#pragma unroll
            for (int hl = 0; hl < 2; hl++) {
                float v = hsum[mt][rf][hl];
                v += __shfl_xor_sync(0xffffffffu, v, 1);
                v += __shfl_xor_sync(0xffffffffu, v, 2);
                if (q4 == 0) {
                    int p = sm_perm[R0 + mt * 16 + rf * 8 + rquad];
                    if (p >= 0) {
                        int h = wc * 2 + hl;
                        out[(size_t)p * 8 + h] = v;
                    }
                }
            }

    cp_async_wait0();
    __syncthreads();

    // =================== phase 1: messages ===================
    float accm[2][4][2][4];   // [nh][mt][ntl][v]
#pragma unroll
    for (int nh = 0; nh < 2; nh++) {
#pragma unroll
        for (int mt = 0; mt < 4; mt++)
#pragma unroll
            for (int ntl = 0; ntl < 2; ntl++)
#pragma unroll
                for (int v = 0; v < 4; v++) accm[nh][mt][ntl][v] = 0.f;
#pragma unroll
        for (int k = 0; k < 8; k++) {
            uint32_t kb = (uint32_t)(k * 32);
            uint32_t bf[4];
            ldmx4(bf, bB + bOff4 + nh * 16 * 272 + kb);
#pragma unroll
            for (int mt = 0; mt < 4; mt++) {
                uint32_t af[4];
                ldmx4(af, aB + aOff + mt * 16 * 272 + kb);
                mma16816(accm[nh][mt][0], af, bf);
                mma16816(accm[nh][mt][1], af, bf + 2);
            }
        }
    }
    __syncthreads();   // all A/B reads done -> overlay M tile

    // STS: acc (+bias) -> fp32 M tile (stride MSTRIDE floats)
    {
        float* mt32 = (float*)dyn;
#pragma unroll
        for (int nh = 0; nh < 2; nh++)
#pragma unroll
            for (int mt = 0; mt < 4; mt++) {
                int r1 = R0 + mt * 16 + rquad;
#pragma unroll
                for (int ntl = 0; ntl < 2; ntl++) {
                    int col = C0 + nh * 16 + ntl * 8 + q4 * 2;
                    float b0 = sBm[col], b1 = sBm[col + 1];
                    *(float2*)(mt32 + r1 * MSTRIDE + col) =
                        make_float2(accm[nh][mt][ntl][0] + b0,
                                    accm[nh][mt][ntl][1] + b1);
                    *(float2*)(mt32 + (r1 + 8) * MSTRIDE + col) =
                        make_float2(accm[nh][mt][ntl][2] + b0,
                                    accm[nh][mt][ntl][3] + b1);
                }
            }
    }
    __syncthreads();

    // coalesced streaming STG: warp per 2 rows, full 512B lines
    {
        const float* mt32 = (const float*)dyn;
        float* mout = out + (size_t)E_EDGES * 8;
        int rowInWarp = lane >> 4;
        int c16 = lane & 15;
#pragma unroll
        for (int rb = 0; rb < 8; rb++) {
            int row = rb * 16 + w * 2 + rowInWarp;
            int p = sm_perm[row];
            if (p >= 0) {
                float* dst = mout + (size_t)p * 128;
                const float* src = mt32 + row * MSTRIDE;
#pragma unroll
                for (int j = 0; j < 2; j++) {
                    int c4 = c16 + 16 * j;
                    float4 v = *(const float4*)(src + c4 * 4);
                    stg_cs_128(dst + c4 * 4, v);
                }
            }
        }
    }
}

// ---------------- launch ----------------
extern "C" void kernel_launch(void* const* d_in, const int* in_sizes, int n_in,
                              void* d_out, int out_size) {
    const int*   etype = (const int*)d_in[0];
    const int*   tau   = (const int*)d_in[1];
    const float* h_s   = (const float*)d_in[2];
    const float* Q_t   = (const float*)d_in[3];
    const int*   dtv   = (const int*)d_in[4];
    const float* emb   = (const float*)d_in[5];
    const float* linW  = (const float*)d_in[6];
    const float* linb  = (const float*)d_in[7];
    const float* K_W   = (const float*)d_in[8];
    const float* K_b   = (const float*)d_in[9];
    const float* V_W   = (const float*)d_in[10];
    const float* V_b   = (const float*)d_in[11];
    const float* Watt  = (const float*)d_in[12];
    const float* Wmsg  = (const float*)d_in[13];
    const float* mu    = (const float*)d_in[14];
    float* out = (float*)d_out;

    cudaFuncSetAttribute(k_main, cudaFuncAttributeMaxDynamicSharedMemorySize, DYN_SMEM);

    k_setup<<<SETUP_GRID, 256>>>(emb, linW, linb, etype, tau,
                                 K_W, K_b, V_W, V_b, Watt, Wmsg, mu);
    k_scatter<<<E_EDGES / 256, 256>>>(etype, tau);
    k_main<<<MAXBLK, 256, DYN_SMEM>>>(h_s, Q_t, dtv, out);
}

// round 14
// speedup vs baseline: 1.3920x; 1.2518x over previous
#include <cuda_runtime.h>
#include <cuda_fp16.h>
#include <cstdint>

#define E_EDGES 131072
#define INS 128
#define OUTS 128
#define NH 8
#define NG 32          /* tau(4) x etype(8) combined groups */
#define ML 240
#define TILE 128
#define MAXBLK (E_EDGES / TILE + NG)   /* 1056 */

#define HIST_BLKS  512
#define WC_BLKS    512
#define RTE_BLKS   (ML / 8)            /* 30 */
#define SETUP_GRID (HIST_BLKS + WC_BLKS + RTE_BLKS)   /* 1054 */

// ---------------- device scratch ----------------
__device__ int   g_perm[MAXBLK * TILE];
__device__ int   g_counts[NG];         // zero at load; self-zeroed each replay
__device__ int   g_cursor[NG];
__device__ int   g_done;               // zero at load; self-zeroed each replay
__device__ int   g_blk_info[MAXBLK];   // g | (valid<<8), or -1
__device__ float g_rte[ML * INS];
__device__ __half g_Batt[NG * 16384];  // combined [g][n][k] fp16 (mu/4 folded)
__device__ __half g_Bmsg[NG * 16384];
__device__ float g_bias_att[NG * OUTS];
__device__ float g_bias_msg[NG * OUTS];

// ---------------- helpers ----------------
__device__ __forceinline__ uint32_t smem_u32(const void* p) {
    uint32_t a;
    asm("{ .reg .u64 t; cvta.to.shared.u64 t, %1; cvt.u32.u64 %0, t; }"
        : "=r"(a) : "l"(p));
    return a;
}
__device__ __forceinline__ void ldmx4(uint32_t* r, uint32_t addr) {
    asm volatile("ldmatrix.sync.aligned.m8n8.x4.shared.b16 {%0,%1,%2,%3}, [%4];"
                 : "=r"(r[0]), "=r"(r[1]), "=r"(r[2]), "=r"(r[3]) : "r"(addr));
}
__device__ __forceinline__ void mma16816(float* c, const uint32_t* a, const uint32_t* b) {
    asm volatile(
        "mma.sync.aligned.m16n8k16.row.col.f32.f16.f16.f32 "
        "{%0,%1,%2,%3}, {%4,%5,%6,%7}, {%8,%9}, {%0,%1,%2,%3};"
        : "+f"(c[0]), "+f"(c[1]), "+f"(c[2]), "+f"(c[3])
        : "r"(a[0]), "r"(a[1]), "r"(a[2]), "r"(a[3]), "r"(b[0]), "r"(b[1]));
}
__device__ __forceinline__ void cp_async16(uint32_t saddr, const void* gaddr) {
    asm volatile("cp.async.cg.shared.global [%0], [%1], 16;"
                 :: "r"(saddr), "l"(gaddr));
}
__device__ __forceinline__ void cp_async_commit() {
    asm volatile("cp.async.commit_group;");
}
__device__ __forceinline__ void cp_async_wait0() {
    asm volatile("cp.async.wait_group 0;");
}
__device__ __forceinline__ void stg_cs_128(float* p, float4 v) {
    asm volatile("st.global.cs.v4.f32 [%0], {%1,%2,%3,%4};"
                 :: "l"(p), "f"(v.x), "f"(v.y), "f"(v.z), "f"(v.w) : "memory");
}

// ---------------- fused setup: hist(+offsets) | weight-combine | RTE (R13-proven) ----------------
#define SBUF_FLOATS (32 * 129 + 8 * 128)   /* 5152 floats = 20608 B */

__global__ void k_setup(const float* __restrict__ emb,
                        const float* __restrict__ linW,
                        const float* __restrict__ linb,
                        const int* __restrict__ etype,
                        const int* __restrict__ tau,
                        const float* __restrict__ K_W, const float* __restrict__ K_b,
                        const float* __restrict__ V_W, const float* __restrict__ V_b,
                        const float* __restrict__ Watt, const float* __restrict__ Wmsg,
                        const float* __restrict__ mu) {
    __shared__ float sbuf[SBUF_FLOATS];
    __shared__ int   sc[NG];
    __shared__ int   seg[NG + 1];
    __shared__ int   cnt[NG];
    __shared__ int   isLast;

    int b = blockIdx.x;
    int tid = threadIdx.x;

    if (b < HIST_BLKS) {
        if (tid < NG) sc[tid] = 0;
        __syncthreads();
        int i = b * 256 + tid;
        atomicAdd(&sc[tau[i] * 8 + etype[i]], 1);
        __syncthreads();
        if (tid < NG && sc[tid] > 0)
            atomicAdd(&g_counts[tid], sc[tid]);

        if (tid == 0) {
            __threadfence();
            isLast = (atomicAdd(&g_done, 1) == HIST_BLKS - 1);
        }
        __syncthreads();
        if (!isLast) return;

        if (tid == 0) {
            int blk = 0;
            for (int g = 0; g < NG; g++) {
                seg[g] = blk;
                int c = g_counts[g];
                cnt[g] = c;
                g_cursor[g] = blk * TILE;
                g_counts[g] = 0;         // self-reset for next graph replay
                blk += (c + TILE - 1) / TILE;
            }
            seg[NG] = blk;
            g_done = 0;                  // self-reset
        }
        __syncthreads();
        int total = seg[NG];
        for (int bb = tid; bb < MAXBLK; bb += blockDim.x) {
            int info = -1;
            if (bb < total) {
                int g = 0;
                for (int q = 1; q < NG; q++)
                    if (bb >= seg[q]) g = q;
                int rem = cnt[g] - (bb - seg[g]) * TILE;
                int valid = rem < TILE ? rem : TILE;
                info = g | (valid << 8);
            }
            g_blk_info[bb] = info;
        }
    } else if (b < HIST_BLKS + WC_BLKS) {
        float* sW1 = sbuf;               // 16*128
        float* sW2 = sbuf + 16 * 128;    // 256
        float* sB1 = sW2 + 256;          // 16

        int q = b - HIST_BLKS;           // 0..511
        int which = q >> 8;              // 0 = att, 1 = msg
        int rem = q & 255;
        int g = rem >> 3, h = rem & 7;
        int t = g >> 3, et = g & 7;

        const float* W1 = (which ? V_W : K_W) + t * 16384 + h * 16 * 128;
        const float* W2 = (which ? Wmsg : Watt) + et * 256;
        const float* b1 = (which ? V_b : K_b) + t * 128 + h * 16;

#pragma unroll
        for (int it = 0; it < 8; it++) sW1[tid + it * 256] = W1[tid + it * 256];
        sW2[tid & 255] = W2[tid & 255];
        if (tid < 16) sB1[tid] = b1[tid];
        __syncthreads();

        float sc2 = which ? 1.0f : mu[et * NH + h] * 0.25f;
        int i = tid & 127;
        int half = tid >> 7;
        __half* dstW = (which ? g_Bmsg : g_Batt) + g * 16384 + h * 16 * 128;
        float* dstB = (which ? g_bias_msg : g_bias_att) + g * 128 + h * 16;

#pragma unroll
        for (int jj = 0; jj < 8; jj++) {
            int o = jj * 2 + half;
            const float* w2 = sW2 + o * 16;
            float acc = 0.f;
#pragma unroll
            for (int k = 0; k < 16; k++) acc += w2[k] * sW1[k * 128 + i];
            dstW[o * 128 + i] = __float2half_rn(acc * sc2);
            if (i == 0) {
                float bacc = 0.f;
#pragma unroll
                for (int k = 0; k < 16; k++) bacc += w2[k] * sB1[k];
                dstB[o] = bacc * sc2;
            }
        }
    } else {
        float* sW = sbuf;                // [32][129]
        float* sE = sbuf + 32 * 129;     // [8][128]
        int d0 = (b - HIST_BLKS - WC_BLKS) * 8;

        for (int idx = tid; idx < 8 * 128; idx += 256)
            sE[idx] = emb[d0 * 128 + idx];

        int oLoc = tid & 31;
        int d = tid >> 5;                // 0..7
        const float* e = sE + d * 128;
        const float* w = sW + oLoc * 129;
#pragma unroll
        for (int qp = 0; qp < 4; qp++) {
            __syncthreads();
            for (int idx = tid; idx < 32 * 128; idx += 256) {
                int o = idx >> 7, i = idx & 127;
                sW[o * 129 + i] = linW[(qp * 32 + o) * 128 + i];
            }
            __syncthreads();
            int o = qp * 32 + oLoc;
            float acc = linb[o];
#pragma unroll 8
            for (int i = 0; i < 128; i++) acc += e[i] * w[i];
            g_rte[(d0 + d) * 128 + o] = acc;
        }
    }
}

// scatter (R12-proven)
__global__ void k_scatter(const int* __restrict__ etype, const int* __restrict__ tau) {
    __shared__ int lcount[NG];
    __shared__ int lbase[NG];
    int tid = threadIdx.x;
    if (tid < NG) lcount[tid] = 0;
    __syncthreads();
    int i = blockIdx.x * blockDim.x + tid;
    int g = tau[i] * 8 + etype[i];
    int rank = atomicAdd(&lcount[g], 1);
    __syncthreads();
    if (tid < NG && lcount[tid] > 0)
        lbase[tid] = atomicAdd(&g_cursor[tid], lcount[tid]);
    __syncthreads();
    g_perm[lbase[g] + rank] = i;
}

// ---------------- main kernel: full-width acc, 3 resident tiles, occ 2 ----------------
#define TILE_B  (TILE * 272)           /* 34816 bytes per padded fp16 tile */
#define SM_A    0
#define SM_BATT TILE_B
#define SM_BMSG (2 * TILE_B)
#define DYN_SMEM (3 * TILE_B)          /* 104448 */
#define MSTRIDE 136                    /* fp32 M-tile row stride (floats) */

__global__ __launch_bounds__(256, 2) void k_main(
    const float* __restrict__ h_s, const float* __restrict__ Q_t,
    const int* __restrict__ dtv, float* __restrict__ out) {
    extern __shared__ char dyn[];
    __shared__ int   sm_perm[TILE];
    __shared__ float sBa[OUTS];
    __shared__ float sBm[OUTS];

    int b = blockIdx.x;
    int info = g_blk_info[b];
    if (info < 0) return;
    int g = info & 31;
    int valid = info >> 8;

    int tid = threadIdx.x;
    int lane = tid & 31;
    int w = tid >> 5;
    int wr = w >> 2, wc = w & 3;
    int R0 = wr * 64, C0 = wc * 32;
    uint32_t sb = smem_u32(dyn);

    // ---- 1) BOTH weight tiles via cp.async (latency hidden behind A build)
    {
        const uint4* s0 = (const uint4*)(g_Batt + g * 16384);
        const uint4* s1 = (const uint4*)(g_Bmsg + g * 16384);
#pragma unroll
        for (int it = 0; it < 8; it++) {
            int idx = tid + it * 256;
            int n = idx >> 4, kc = idx & 15;
            uint32_t off = (uint32_t)(n * 272 + kc * 16);
            cp_async16(sb + SM_BATT + off, s0 + idx);
            cp_async16(sb + SM_BMSG + off, s1 + idx);
        }
        cp_async_commit();
    }

    // ---- 2) per-block constants
    if (tid < TILE) {
        sm_perm[tid] = (tid < valid) ? g_perm[b * TILE + tid] : -1;
        sBa[tid] = g_bias_att[g * 128 + tid];
        sBm[tid] = g_bias_msg[g * 128 + tid];
    }

    // ---- 3) build A tile (fp16) with coalesced h_s reads: warp handles 2 rows
    {
        int rowInWarp = lane >> 4;           // 0 or 1
        int c16 = lane & 15;                 // float4 index within half-row
#pragma unroll
        for (int rb = 0; rb < 8; rb++) {
            int row = rb * 16 + w * 2 + rowInWarp;
            int p = (row < valid) ? g_perm[b * TILE + row] : -1;
            const float4* hs4 = (const float4*)(h_s + (size_t)(p < 0 ? 0 : p) * 128);
            int d = (p >= 0) ? dtv[p] : 0;
            const float4* rt4 = (const float4*)(g_rte + d * 128);
            char* smA = dyn + SM_A + row * 272;
#pragma unroll
            for (int j = 0; j < 2; j++) {
                int c4 = c16 + 16 * j;       // 0..31
                float v0 = 0.f, v1 = 0.f, v2 = 0.f, v3 = 0.f;
                if (p >= 0) {
                    float4 hv = hs4[c4];
                    float4 rv = rt4[c4];
                    v0 = hv.x + rv.x; v1 = hv.y + rv.y;
                    v2 = hv.z + rv.z; v3 = hv.w + rv.w;
                }
                __half2 h01 = __floats2half2_rn(v0, v1);
                __half2 h23 = __floats2half2_rn(v2, v3);
                uint2 pk;
                pk.x = *reinterpret_cast<unsigned*>(&h01);
                pk.y = *reinterpret_cast<unsigned*>(&h23);
                *(uint2*)(smA + c4 * 8) = pk;
            }
        }
    }
    cp_async_wait0();
    __syncthreads();

    uint32_t aB = sb + SM_A;
    uint32_t aOff = (uint32_t)((R0 + (lane & 15)) * 272 + (lane >> 4) * 16);
    uint32_t bOff4 = (uint32_t)((C0 + (lane & 7) + ((lane >> 4) & 1) * 8) * 272 +
                                ((lane >> 3) & 1) * 16);
    int q4 = lane & 3, rquad = lane >> 2;

    // =================== phase 0: attention (full 32-col acc) ===================
    float acc[4][4][4];   // [mt][ntl][v], ntl over 4 8-col groups
#pragma unroll
    for (int mt = 0; mt < 4; mt++)
#pragma unroll
        for (int ntl = 0; ntl < 4; ntl++)
#pragma unroll
            for (int v = 0; v < 4; v++) acc[mt][ntl][v] = 0.f;

    {
        uint32_t bB = sb + SM_BATT;
#pragma unroll
        for (int k = 0; k < 8; k++) {
            uint32_t kb = (uint32_t)(k * 32);
            uint32_t bf0[4], bf1[4];
            ldmx4(bf0, bB + bOff4 + kb);               // cols C0..C0+15
            ldmx4(bf1, bB + bOff4 + 16 * 272 + kb);    // cols C0+16..C0+31
#pragma unroll
            for (int mt = 0; mt < 4; mt++) {
                uint32_t af[4];
                ldmx4(af, aB + aOff + mt * 16 * 272 + kb);
                mma16816(acc[mt][0], af, bf0);
                mma16816(acc[mt][1], af, bf0 + 2);
                mma16816(acc[mt][2], af, bf1);
                mma16816(acc[mt][3], af, bf1 + 2);
            }
        }
    }

    // att epilogue: hsum over o, Q gather, shuffle-reduce, store
    {
        float hsum[4][2][2];
#pragma unroll
        for (int mt = 0; mt < 4; mt++)
#pragma unroll
            for (int rf = 0; rf < 2; rf++)
#pragma unroll
                for (int hl = 0; hl < 2; hl++) hsum[mt][rf][hl] = 0.f;
#pragma unroll
        for (int mt = 0; mt < 4; mt++) {
            int p1 = sm_perm[R0 + mt * 16 + rquad];
            int p2 = sm_perm[R0 + mt * 16 + rquad + 8];
            const float* q1base = Q_t + (size_t)(p1 < 0 ? 0 : p1) * 128;
            const float* q2base = Q_t + (size_t)(p2 < 0 ? 0 : p2) * 128;
#pragma unroll
            for (int ntl = 0; ntl < 4; ntl++) {
                int col = C0 + ntl * 8 + q4 * 2;
                float b0 = sBa[col], b1 = sBa[col + 1];
                int hl = ntl >> 1;
                float2 q1 = __ldg((const float2*)(q1base + col));
                float2 q2 = __ldg((const float2*)(q2base + col));
                hsum[mt][0][hl] += (acc[mt][ntl][0] + b0) * q1.x +
                                   (acc[mt][ntl][1] + b1) * q1.y;
                hsum[mt][1][hl] += (acc[mt][ntl][2] + b0) * q2.x +
                                   (acc[mt][ntl][3] + b1) * q2.y;
            }
        }
#pragma unroll
        for (int mt = 0; mt < 4; mt++)
#pragma unroll
            for (int rf = 0; rf < 2; rf++)
#pragma unroll
                for (int hl = 0; hl < 2; hl++) {
                    float v = hsum[mt][rf][hl];
                    v += __shfl_xor_sync(0xffffffffu, v, 1);
                    v += __shfl_xor_sync(0xffffffffu, v, 2);
                    if (q4 == 0) {
                        int p = sm_perm[R0 + mt * 16 + rf * 8 + rquad];
                        if (p >= 0) {
                            int h = wc * 2 + hl;
                            out[(size_t)p * 8 + h] = v;
                        }
                    }
                }
    }

    // =================== phase 1: messages (no barrier needed) ===================
#pragma unroll
    for (int mt = 0; mt < 4; mt++)
#pragma unroll
        for (int ntl = 0; ntl < 4; ntl++)
#pragma unroll
            for (int v = 0; v < 4; v++) acc[mt][ntl][v] = 0.f;

    {
        uint32_t bB = sb + SM_BMSG;
#pragma unroll
        for (int k = 0; k < 8; k++) {
            uint32_t kb = (uint32_t)(k * 32);
            uint32_t bf0[4], bf1[4];
            ldmx4(bf0, bB + bOff4 + kb);
            ldmx4(bf1, bB + bOff4 + 16 * 272 + kb);
#pragma unroll
            for (int mt = 0; mt < 4; mt++) {
                uint32_t af[4];
                ldmx4(af, aB + aOff + mt * 16 * 272 + kb);
                mma16816(acc[mt][0], af, bf0);
                mma16816(acc[mt][1], af, bf0 + 2);
                mma16816(acc[mt][2], af, bf1);
                mma16816(acc[mt][3], af, bf1 + 2);
            }
        }
    }
    __syncthreads();   // all A/Batt reads done -> overlay M tile over [A|Batt]

    // STS: acc (+bias) -> fp32 M tile (stride MSTRIDE floats)
    {
        float* mt32 = (float*)dyn;
#pragma unroll
        for (int mt = 0; mt < 4; mt++) {
            int r1 = R0 + mt * 16 + rquad;
#pragma unroll
            for (int ntl = 0; ntl < 4; ntl++) {
                int col = C0 + ntl * 8 + q4 * 2;
                float b0 = sBm[col], b1 = sBm[col + 1];
                *(float2*)(mt32 + r1 * MSTRIDE + col) =
                    make_float2(acc[mt][ntl][0] + b0, acc[mt][ntl][1] + b1);
                *(float2*)(mt32 + (r1 + 8) * MSTRIDE + col) =
                    make_float2(acc[mt][ntl][2] + b0, acc[mt][ntl][3] + b1);
            }
        }
    }
    __syncthreads();

    // coalesced streaming STG: warp per 2 rows, full 512B lines
    {
        const float* mt32 = (const float*)dyn;
        float* mout = out + (size_t)E_EDGES * 8;
        int rowInWarp = lane >> 4;
        int c16 = lane & 15;
#pragma unroll
        for (int rb = 0; rb < 8; rb++) {
            int row = rb * 16 + w * 2 + rowInWarp;
            int p = sm_perm[row];
            if (p >= 0) {
                float* dst = mout + (size_t)p * 128;
                const float* src = mt32 + row * MSTRIDE;
#pragma unroll
                for (int j = 0; j < 2; j++) {
                    int c4 = c16 + 16 * j;
                    float4 v = *(const float4*)(src + c4 * 4);
                    stg_cs_128(dst + c4 * 4, v);
                }
            }
        }
    }
}

// ---------------- launch ----------------
extern "C" void kernel_launch(void* const* d_in, const int* in_sizes, int n_in,
                              void* d_out, int out_size) {
    const int*   etype = (const int*)d_in[0];
    const int*   tau   = (const int*)d_in[1];
    const float* h_s   = (const float*)d_in[2];
    const float* Q_t   = (const float*)d_in[3];
    const int*   dtv   = (const int*)d_in[4];
    const float* emb   = (const float*)d_in[5];
    const float* linW  = (const float*)d_in[6];
    const float* linb  = (const float*)d_in[7];
    const float* K_W   = (const float*)d_in[8];
    const float* K_b   = (const float*)d_in[9];
    const float* V_W   = (const float*)d_in[10];
    const float* V_b   = (const float*)d_in[11];
    const float* Watt  = (const float*)d_in[12];
    const float* Wmsg  = (const float*)d_in[13];
    const float* mu    = (const float*)d_in[14];
    float* out = (float*)d_out;

    cudaFuncSetAttribute(k_main, cudaFuncAttributeMaxDynamicSharedMemorySize, DYN_SMEM);

    k_setup<<<SETUP_GRID, 256>>>(emb, linW, linb, etype, tau,
                                 K_W, K_b, V_W, V_b, Watt, Wmsg, mu);
    k_scatter<<<E_EDGES / 256, 256>>>(etype, tau);
    k_main<<<MAXBLK, 256, DYN_SMEM>>>(h_s, Q_t, dtv, out);
}

// round 15
// speedup vs baseline: 1.4649x; 1.0523x over previous
#include <cuda_runtime.h>
#include <cuda_fp16.h>
#include <cstdint>

#define E_EDGES 131072
#define INS 128
#define OUTS 128
#define NH 8
#define NG 32          /* tau(4) x etype(8) combined groups */
#define ML 240
#define TILE 128
#define MAXBLK (E_EDGES / TILE + NG)   /* 1056 */

#define HIST_BLKS  256                 /* 2 edges/thread */
#define WC_BLKS    512
#define RTE_BLKS   (ML / 8)            /* 30 */
#define SETUP_GRID (HIST_BLKS + WC_BLKS + RTE_BLKS)   /* 798 */

// ---------------- device scratch ----------------
__device__ int   g_perm[MAXBLK * TILE];
__device__ int   g_counts[NG];         // zero at load; self-zeroed each replay
__device__ int   g_cursor[NG];
__device__ int   g_done;               // zero at load; self-zeroed each replay
__device__ int   g_blk_info[MAXBLK];   // g | (valid<<8), or -1
__device__ float g_rte[ML * INS];
__device__ __half g_Batt[NG * 16384];  // combined [g][n][k] fp16 (mu/4 folded)
__device__ __half g_Bmsg[NG * 16384];
__device__ float g_bias_att[NG * OUTS];
__device__ float g_bias_msg[NG * OUTS];

// ---------------- helpers ----------------
__device__ __forceinline__ uint32_t smem_u32(const void* p) {
    uint32_t a;
    asm("{ .reg .u64 t; cvta.to.shared.u64 t, %1; cvt.u32.u64 %0, t; }"
        : "=r"(a) : "l"(p));
    return a;
}
__device__ __forceinline__ void ldmx4(uint32_t* r, uint32_t addr) {
    asm volatile("ldmatrix.sync.aligned.m8n8.x4.shared.b16 {%0,%1,%2,%3}, [%4];"
                 : "=r"(r[0]), "=r"(r[1]), "=r"(r[2]), "=r"(r[3]) : "r"(addr));
}
__device__ __forceinline__ void mma16816(float* c, const uint32_t* a, const uint32_t* b) {
    asm volatile(
        "mma.sync.aligned.m16n8k16.row.col.f32.f16.f16.f32 "
        "{%0,%1,%2,%3}, {%4,%5,%6,%7}, {%8,%9}, {%0,%1,%2,%3};"
        : "+f"(c[0]), "+f"(c[1]), "+f"(c[2]), "+f"(c[3])
        : "r"(a[0]), "r"(a[1]), "r"(a[2]), "r"(a[3]), "r"(b[0]), "r"(b[1]));
}
__device__ __forceinline__ void cp_async16(uint32_t saddr, const void* gaddr) {
    asm volatile("cp.async.cg.shared.global [%0], [%1], 16;"
                 :: "r"(saddr), "l"(gaddr));
}
__device__ __forceinline__ void cp_async_commit() {
    asm volatile("cp.async.commit_group;");
}
__device__ __forceinline__ void cp_async_wait0() {
    asm volatile("cp.async.wait_group 0;");
}
__device__ __forceinline__ void stg_cs_128(float* p, float4 v) {
    asm volatile("st.global.cs.v4.f32 [%0], {%1,%2,%3,%4};"
                 :: "l"(p), "f"(v.x), "f"(v.y), "f"(v.z), "f"(v.w) : "memory");
}
__device__ __forceinline__ void prefetch_l2(const void* p) {
    asm volatile("prefetch.global.L2 [%0];" :: "l"(p));
}

// ---------------- fused setup: hist(+offsets) | weight-combine | RTE ----------------
#define SBUF_FLOATS (32 * 129 + 8 * 128)   /* 5152 floats = 20608 B */

__global__ void k_setup(const float* __restrict__ emb,
                        const float* __restrict__ linW,
                        const float* __restrict__ linb,
                        const int* __restrict__ etype,
                        const int* __restrict__ tau,
                        const float* __restrict__ K_W, const float* __restrict__ K_b,
                        const float* __restrict__ V_W, const float* __restrict__ V_b,
                        const float* __restrict__ Watt, const float* __restrict__ Wmsg,
                        const float* __restrict__ mu) {
    __shared__ float sbuf[SBUF_FLOATS];
    __shared__ int   sc[NG];
    __shared__ int   seg[NG + 1];
    __shared__ int   cnt[NG];
    __shared__ int   isLast;

    int b = blockIdx.x;
    int tid = threadIdx.x;

    if (b < HIST_BLKS) {
        if (tid < NG) sc[tid] = 0;
        __syncthreads();
        int i0 = b * 512 + tid;
        atomicAdd(&sc[tau[i0] * 8 + etype[i0]], 1);
        atomicAdd(&sc[tau[i0 + 256] * 8 + etype[i0 + 256]], 1);
        __syncthreads();
        if (tid < NG && sc[tid] > 0)
            atomicAdd(&g_counts[tid], sc[tid]);

        if (tid == 0) {
            __threadfence();
            isLast = (atomicAdd(&g_done, 1) == HIST_BLKS - 1);
        }
        __syncthreads();
        if (!isLast) return;

        if (tid == 0) {
            int blk = 0;
            for (int g = 0; g < NG; g++) {
                seg[g] = blk;
                int c = g_counts[g];
                cnt[g] = c;
                g_cursor[g] = blk * TILE;
                g_counts[g] = 0;         // self-reset for next graph replay
                blk += (c + TILE - 1) / TILE;
            }
            seg[NG] = blk;
            g_done = 0;                  // self-reset
        }
        __syncthreads();
        int total = seg[NG];
        for (int bb = tid; bb < MAXBLK; bb += blockDim.x) {
            int info = -1;
            if (bb < total) {
                int g = 0;
                for (int q = 1; q < NG; q++)
                    if (bb >= seg[q]) g = q;
                int rem = cnt[g] - (bb - seg[g]) * TILE;
                int valid = rem < TILE ? rem : TILE;
                info = g | (valid << 8);
            }
            g_blk_info[bb] = info;
        }
    } else if (b < HIST_BLKS + WC_BLKS) {
        float* sW1 = sbuf;               // 16*128
        float* sW2 = sbuf + 16 * 128;    // 256
        float* sB1 = sW2 + 256;          // 16

        int q = b - HIST_BLKS;           // 0..511
        int which = q >> 8;              // 0 = att, 1 = msg
        int rem = q & 255;
        int g = rem >> 3, h = rem & 7;
        int t = g >> 3, et = g & 7;

        const float* W1 = (which ? V_W : K_W) + t * 16384 + h * 16 * 128;
        const float* W2 = (which ? Wmsg : Watt) + et * 256;
        const float* b1 = (which ? V_b : K_b) + t * 128 + h * 16;

#pragma unroll
        for (int it = 0; it < 8; it++) sW1[tid + it * 256] = W1[tid + it * 256];
        sW2[tid & 255] = W2[tid & 255];
        if (tid < 16) sB1[tid] = b1[tid];
        __syncthreads();

        float sc2 = which ? 1.0f : mu[et * NH + h] * 0.25f;
        int i = tid & 127;
        int half = tid >> 7;
        __half* dstW = (which ? g_Bmsg : g_Batt) + g * 16384 + h * 16 * 128;
        float* dstB = (which ? g_bias_msg : g_bias_att) + g * 128 + h * 16;

#pragma unroll
        for (int jj = 0; jj < 8; jj++) {
            int o = jj * 2 + half;
            const float* w2 = sW2 + o * 16;
            float acc = 0.f;
#pragma unroll
            for (int k = 0; k < 16; k++) acc += w2[k] * sW1[k * 128 + i];
            dstW[o * 128 + i] = __float2half_rn(acc * sc2);
            if (i == 0) {
                float bacc = 0.f;
#pragma unroll
                for (int k = 0; k < 16; k++) bacc += w2[k] * sB1[k];
                dstB[o] = bacc * sc2;
            }
        }
    } else {
        float* sW = sbuf;                // [32][129]
        float* sE = sbuf + 32 * 129;     // [8][128]
        int d0 = (b - HIST_BLKS - WC_BLKS) * 8;

        for (int idx = tid; idx < 8 * 128; idx += 256)
            sE[idx] = emb[d0 * 128 + idx];

        int oLoc = tid & 31;
        int d = tid >> 5;                // 0..7
        const float* e = sE + d * 128;
        const float* w = sW + oLoc * 129;
#pragma unroll
        for (int qp = 0; qp < 4; qp++) {
            __syncthreads();
            for (int idx = tid; idx < 32 * 128; idx += 256) {
                int o = idx >> 7, i = idx & 127;
                sW[o * 129 + i] = linW[(qp * 32 + o) * 128 + i];
            }
            __syncthreads();
            int o = qp * 32 + oLoc;
            float acc = linb[o];
#pragma unroll 8
            for (int i = 0; i < 128; i++) acc += e[i] * w[i];
            g_rte[(d0 + d) * 128 + o] = acc;
        }
    }
}

// scatter (R12-proven)
__global__ void k_scatter(const int* __restrict__ etype, const int* __restrict__ tau) {
    __shared__ int lcount[NG];
    __shared__ int lbase[NG];
    int tid = threadIdx.x;
    if (tid < NG) lcount[tid] = 0;
    __syncthreads();
    int i = blockIdx.x * blockDim.x + tid;
    int g = tau[i] * 8 + etype[i];
    int rank = atomicAdd(&lcount[g], 1);
    __syncthreads();
    if (tid < NG && lcount[tid] > 0)
        lbase[tid] = atomicAdd(&g_cursor[tid], lcount[tid]);
    __syncthreads();
    g_perm[lbase[g] + rank] = i;
}

// ---------------- main kernel: full-width acc, 3 resident tiles, occ 2 ----------------
#define TILE_B  (TILE * 272)           /* 34816 bytes per padded fp16 tile */
#define SM_A    0
#define SM_BATT TILE_B
#define SM_BMSG (2 * TILE_B)
#define DYN_SMEM (3 * TILE_B)          /* 104448 */
#define MSTRIDE 132                    /* fp32 M-tile row stride (floats), bank-spread */

__global__ __launch_bounds__(256, 2) void k_main(
    const float* __restrict__ h_s, const float* __restrict__ Q_t,
    const int* __restrict__ dtv, float* __restrict__ out) {
    extern __shared__ char dyn[];
    __shared__ int   sm_perm[TILE];
    __shared__ float sBa[OUTS];
    __shared__ float sBm[OUTS];

    int b = blockIdx.x;
    int info = g_blk_info[b];
    if (info < 0) return;
    int g = info & 31;
    int valid = info >> 8;

    int tid = threadIdx.x;
    int lane = tid & 31;
    int w = tid >> 5;
    int wr = w >> 2, wc = w & 3;
    int R0 = wr * 64, C0 = wc * 32;
    uint32_t sb = smem_u32(dyn);

    // ---- 0) L2-prefetch Q rows for the att epilogue (hidden behind MMA)
    {
        int row = tid >> 1;
        int p = (row < valid) ? g_perm[b * TILE + row] : -1;
        if (p >= 0) {
            const char* q = (const char*)(Q_t + (size_t)p * 128) + (tid & 1) * 256;
            prefetch_l2(q);
            prefetch_l2(q + 128);
        }
    }

    // ---- 1) BOTH weight tiles via cp.async (latency hidden behind A build)
    {
        const uint4* s0 = (const uint4*)(g_Batt + g * 16384);
        const uint4* s1 = (const uint4*)(g_Bmsg + g * 16384);
#pragma unroll
        for (int it = 0; it < 8; it++) {
            int idx = tid + it * 256;
            int n = idx >> 4, kc = idx & 15;
            uint32_t off = (uint32_t)(n * 272 + kc * 16);
            cp_async16(sb + SM_BATT + off, s0 + idx);
            cp_async16(sb + SM_BMSG + off, s1 + idx);
        }
        cp_async_commit();
    }

    // ---- 2) per-block constants
    if (tid < TILE) {
        sm_perm[tid] = (tid < valid) ? g_perm[b * TILE + tid] : -1;
        sBa[tid] = g_bias_att[g * 128 + tid];
        sBm[tid] = g_bias_msg[g * 128 + tid];
    }

    // ---- 3) build A tile (fp16) with coalesced h_s reads: warp handles 2 rows
    {
        int rowInWarp = lane >> 4;           // 0 or 1
        int c16 = lane & 15;                 // float4 index within half-row
#pragma unroll
        for (int rb = 0; rb < 8; rb++) {
            int row = rb * 16 + w * 2 + rowInWarp;
            int p = (row < valid) ? g_perm[b * TILE + row] : -1;
            const float4* hs4 = (const float4*)(h_s + (size_t)(p < 0 ? 0 : p) * 128);
            int d = (p >= 0) ? dtv[p] : 0;
            const float4* rt4 = (const float4*)(g_rte + d * 128);
            char* smA = dyn + SM_A + row * 272;
#pragma unroll
            for (int j = 0; j < 2; j++) {
                int c4 = c16 + 16 * j;       // 0..31
                float v0 = 0.f, v1 = 0.f, v2 = 0.f, v3 = 0.f;
                if (p >= 0) {
                    float4 hv = hs4[c4];
                    float4 rv = rt4[c4];
                    v0 = hv.x + rv.x; v1 = hv.y + rv.y;
                    v2 = hv.z + rv.z; v3 = hv.w + rv.w;
                }
                __half2 h01 = __floats2half2_rn(v0, v1);
                __half2 h23 = __floats2half2_rn(v2, v3);
                uint2 pk;
                pk.x = *reinterpret_cast<unsigned*>(&h01);
                pk.y = *reinterpret_cast<unsigned*>(&h23);
                *(uint2*)(smA + c4 * 8) = pk;
            }
        }
    }
    cp_async_wait0();
    __syncthreads();

    uint32_t aB = sb + SM_A;
    uint32_t aOff = (uint32_t)((R0 + (lane & 15)) * 272 + (lane >> 4) * 16);
    uint32_t bOff4 = (uint32_t)((C0 + (lane & 7) + ((lane >> 4) & 1) * 8) * 272 +
                                ((lane >> 3) & 1) * 16);
    int q4 = lane & 3, rquad = lane >> 2;

    // =================== phase 0: attention (full 32-col acc) ===================
    float acc[4][4][4];   // [mt][ntl][v], ntl over 4 8-col groups
#pragma unroll
    for (int mt = 0; mt < 4; mt++)
#pragma unroll
        for (int ntl = 0; ntl < 4; ntl++)
#pragma unroll
            for (int v = 0; v < 4; v++) acc[mt][ntl][v] = 0.f;

    {
        uint32_t bB = sb + SM_BATT;
#pragma unroll
        for (int k = 0; k < 8; k++) {
            uint32_t kb = (uint32_t)(k * 32);
            uint32_t bf0[4], bf1[4];
            ldmx4(bf0, bB + bOff4 + kb);               // cols C0..C0+15
            ldmx4(bf1, bB + bOff4 + 16 * 272 + kb);    // cols C0+16..C0+31
#pragma unroll
            for (int mt = 0; mt < 4; mt++) {
                uint32_t af[4];
                ldmx4(af, aB + aOff + mt * 16 * 272 + kb);
                mma16816(acc[mt][0], af, bf0);
                mma16816(acc[mt][1], af, bf0 + 2);
                mma16816(acc[mt][2], af, bf1);
                mma16816(acc[mt][3], af, bf1 + 2);
            }
        }
    }

    // att epilogue: hsum over o, Q gather (L2-warm), shuffle-reduce, store
    {
        float hsum[4][2][2];
#pragma unroll
        for (int mt = 0; mt < 4; mt++)
#pragma unroll
            for (int rf = 0; rf < 2; rf++)
#pragma unroll
                for (int hl = 0; hl < 2; hl++) hsum[mt][rf][hl] = 0.f;
#pragma unroll
        for (int mt = 0; mt < 4; mt++) {
            int p1 = sm_perm[R0 + mt * 16 + rquad];
            int p2 = sm_perm[R0 + mt * 16 + rquad + 8];
            const float* q1base = Q_t + (size_t)(p1 < 0 ? 0 : p1) * 128;
            const float* q2base = Q_t + (size_t)(p2 < 0 ? 0 : p2) * 128;
#pragma unroll
            for (int ntl = 0; ntl < 4; ntl++) {
                int col = C0 + ntl * 8 + q4 * 2;
                float b0 = sBa[col], b1 = sBa[col + 1];
                int hl = ntl >> 1;
                float2 q1 = __ldg((const float2*)(q1base + col));
                float2 q2 = __ldg((const float2*)(q2base + col));
                hsum[mt][0][hl] += (acc[mt][ntl][0] + b0) * q1.x +
                                   (acc[mt][ntl][1] + b1) * q1.y;
                hsum[mt][1][hl] += (acc[mt][ntl][2] + b0) * q2.x +
                                   (acc[mt][ntl][3] + b1) * q2.y;
            }
        }
#pragma unroll
        for (int mt = 0; mt < 4; mt++)
#pragma unroll
            for (int rf = 0; rf < 2; rf++)
#pragma unroll
                for (int hl = 0; hl < 2; hl++) {
                    float v = hsum[mt][rf][hl];
                    v += __shfl_xor_sync(0xffffffffu, v, 1);
                    v += __shfl_xor_sync(0xffffffffu, v, 2);
                    if (q4 == 0) {
                        int p = sm_perm[R0 + mt * 16 + rf * 8 + rquad];
                        if (p >= 0) {
                            int h = wc * 2 + hl;
                            out[(size_t)p * 8 + h] = v;
                        }
                    }
                }
    }

    // =================== phase 1: messages (no barrier needed) ===================
#pragma unroll
    for (int mt = 0; mt < 4; mt++)
#pragma unroll
        for (int ntl = 0; ntl < 4; ntl++)
#pragma unroll
            for (int v = 0; v < 4; v++) acc[mt][ntl][v] = 0.f;

    {
        uint32_t bB = sb + SM_BMSG;
#pragma unroll
        for (int k = 0; k < 8; k++) {
            uint32_t kb = (uint32_t)(k * 32);
            uint32_t bf0[4], bf1[4];
            ldmx4(bf0, bB + bOff4 + kb);
            ldmx4(bf1, bB + bOff4 + 16 * 272 + kb);
#pragma unroll
            for (int mt = 0; mt < 4; mt++) {
                uint32_t af[4];
                ldmx4(af, aB + aOff + mt * 16 * 272 + kb);
                mma16816(acc[mt][0], af, bf0);
                mma16816(acc[mt][1], af, bf0 + 2);
                mma16816(acc[mt][2], af, bf1);
                mma16816(acc[mt][3], af, bf1 + 2);
            }
        }
    }
    __syncthreads();   // all A/Batt reads done -> overlay M tile over [A|Batt]

    // STS: acc (+bias) -> fp32 M tile (stride MSTRIDE floats)
    {
        float* mt32 = (float*)dyn;
#pragma unroll
        for (int mt = 0; mt < 4; mt++) {
            int r1 = R0 + mt * 16 + rquad;
#pragma unroll
            for (int ntl = 0; ntl < 4; ntl++) {
                int col = C0 + ntl * 8 + q4 * 2;
                float b0 = sBm[col], b1 = sBm[col + 1];
                *(float2*)(mt32 + r1 * MSTRIDE + col) =
                    make_float2(acc[mt][ntl][0] + b0, acc[mt][ntl][1] + b1);
                *(float2*)(mt32 + (r1 + 8) * MSTRIDE + col) =
                    make_float2(acc[mt][ntl][2] + b0, acc[mt][ntl][3] + b1);
            }
        }
    }
    __syncthreads();

    // coalesced streaming STG: warp per 2 rows, full 512B lines
    {
        const float* mt32 = (const float*)dyn;
        float* mout = out + (size_t)E_EDGES * 8;
        int rowInWarp = lane >> 4;
        int c16 = lane & 15;
#pragma unroll
        for (int rb = 0; rb < 8; rb++) {
            int row = rb * 16 + w * 2 + rowInWarp;
            int p = sm_perm[row];
            if (p >= 0) {
                float* dst = mout + (size_t)p * 128;
                const float* src = mt32 + row * MSTRIDE;
#pragma unroll
                for (int j = 0; j < 2; j++) {
                    int c4 = c16 + 16 * j;
                    float4 v = *(const float4*)(src + c4 * 4);
                    stg_cs_128(dst + c4 * 4, v);
                }
            }
        }
    }
}

// ---------------- launch ----------------
extern "C" void kernel_launch(void* const* d_in, const int* in_sizes, int n_in,
                              void* d_out, int out_size) {
    const int*   etype = (const int*)d_in[0];
    const int*   tau   = (const int*)d_in[1];
    const float* h_s   = (const float*)d_in[2];
    const float* Q_t   = (const float*)d_in[3];
    const int*   dtv   = (const int*)d_in[4];
    const float* emb   = (const float*)d_in[5];
    const float* linW  = (const float*)d_in[6];
    const float* linb  = (const float*)d_in[7];
    const float* K_W   = (const float*)d_in[8];
    const float* K_b   = (const float*)d_in[9];
    const float* V_W   = (const float*)d_in[10];
    const float* V_b   = (const float*)d_in[11];
    const float* Watt  = (const float*)d_in[12];
    const float* Wmsg  = (const float*)d_in[13];
    const float* mu    = (const float*)d_in[14];
    float* out = (float*)d_out;

    cudaFuncSetAttribute(k_main, cudaFuncAttributeMaxDynamicSharedMemorySize, DYN_SMEM);

    k_setup<<<SETUP_GRID, 256>>>(emb, linW, linb, etype, tau,
                                 K_W, K_b, V_W, V_b, Watt, Wmsg, mu);
    k_scatter<<<E_EDGES / 256, 256>>>(etype, tau);
    k_main<<<MAXBLK, 256, DYN_SMEM>>>(h_s, Q_t, dtv, out);
}